// round 13
// baseline (speedup 1.0000x reference)
#include <cuda_runtime.h>
#include <cuda_fp16.h>
#include <math_constants.h>
#include <cstdint>

#define BB 2
#define LL 2048
#define NH 16
#define DD 64
#define SCALE 0.125f

#define TI 128
#define TJ 64
#define NTJ (LL / TJ)            // 32 j-tiles
#define NROWS (BB * NH * LL)     // 65536 softmax rows
#define PCH 72                   // smem pitch in 16-bit elems (144B rows -> conflict-free LDSM)

// scores scratch: u = exp(masked scaled score) in fp16, layout [b][n][i][j]
__device__ __half g_scores[(size_t)BB * NH * LL * LL];
// per-(row, j-tile) partial sums of u, layout [jt][b][n][i]
__device__ float g_tl[NTJ * NROWS];
// final per-row 1/sum, layout [b][i][n]
__device__ float g_c[BB * LL * NH];
// fp16 operands, layout [b][n][j][d]
__device__ __half g_qh[(size_t)BB * NH * LL * DD];
__device__ __half g_kh[(size_t)BB * NH * LL * DD];
__device__ __half g_vh[(size_t)BB * NH * LL * DD];

// ---------------- portable tensor helpers (sm_80+) ----------------
__device__ __forceinline__ uint32_t smem_u32(const void* p) {
    uint32_t a;
    asm("{ .reg .u64 t; cvta.to.shared.u64 t, %1; cvt.u32.u64 %0, t; }" : "=r"(a) : "l"(p));
    return a;
}
__device__ __forceinline__ void ldmatrix_x4(uint32_t& r0, uint32_t& r1,
                                            uint32_t& r2, uint32_t& r3, uint32_t addr) {
    asm volatile("ldmatrix.sync.aligned.m8n8.x4.shared.b16 {%0,%1,%2,%3}, [%4];"
                 : "=r"(r0), "=r"(r1), "=r"(r2), "=r"(r3) : "r"(addr));
}
__device__ __forceinline__ void ldmatrix_x4_t(uint32_t& r0, uint32_t& r1,
                                              uint32_t& r2, uint32_t& r3, uint32_t addr) {
    asm volatile("ldmatrix.sync.aligned.m8n8.x4.trans.shared.b16 {%0,%1,%2,%3}, [%4];"
                 : "=r"(r0), "=r"(r1), "=r"(r2), "=r"(r3) : "r"(addr));
}
__device__ __forceinline__ void mma_f16(float4& d, const uint32_t a[4],
                                        uint32_t b0, uint32_t b1) {
    asm volatile(
        "mma.sync.aligned.m16n8k16.row.col.f32.f16.f16.f32 "
        "{%0,%1,%2,%3},{%4,%5,%6,%7},{%8,%9},{%0,%1,%2,%3};"
        : "+f"(d.x), "+f"(d.y), "+f"(d.z), "+f"(d.w)
        : "r"(a[0]), "r"(a[1]), "r"(a[2]), "r"(a[3]), "r"(b0), "r"(b1));
}
__device__ __forceinline__ void cp_async16(uint32_t smem, const void* gmem) {
    asm volatile("cp.async.cg.shared.global [%0], [%1], 16;" :: "r"(smem), "l"(gmem));
}
#define CP_COMMIT() asm volatile("cp.async.commit_group;" ::: "memory")
#define CP_WAIT(n)  asm volatile("cp.async.wait_group %0;" :: "n"(n) : "memory")

// ---------------------------------------------------------------------------
// Kernel 0: cast Q,K,V -> fp16, transpose [b,i,n,d] -> [b,n,i,d].
// ---------------------------------------------------------------------------
__global__ __launch_bounds__(256) void k_split(
    const float* __restrict__ q, const float* __restrict__ k,
    const float* __restrict__ v)
{
    int idx = blockIdx.x * 256 + threadIdx.x;   // BB*NH*LL*32
    int d2 = idx & 31;
    int j  = (idx >> 5) & (LL - 1);
    int n  = (idx >> 16) & 15;
    int b  = idx >> 20;
    size_t src = (((size_t)(b * LL + j)) * NH + n) * DD + d2 * 2;
    size_t dst = (((size_t)(b * NH + n)) * LL + j) * DD + d2 * 2;

    float2 xq = *(const float2*)&q[src];
    float2 xk = *(const float2*)&k[src];
    float2 xv = *(const float2*)&v[src];
    *(__half2*)&g_qh[dst] = __floats2half2_rn(xq.x, xq.y);
    *(__half2*)&g_kh[dst] = __floats2half2_rn(xk.x, xk.y);
    *(__half2*)&g_vh[dst] = __floats2half2_rn(xv.x, xv.y);
}

// smem element offsets for k_scores (16-bit units)
#define QHI_OFF 0
#define KHI_OFF (TI * PCH)
#define MSK_OFF ((TI * PCH + TJ * PCH) * 2)               // byte offset of mask
#define SMEM1_BYTES (MSK_OFF + TI * TJ)                   // 27648 + 8192 = 35840 B

// ---------------------------------------------------------------------------
// Kernel 1: HMMA scores (pure fp16: S = Qh*Kh). CTA = (b,n) x 128i x 64j.
// 8 warps, warp = 16i x 64j. Mask prefetched to smem bytes.
// ---------------------------------------------------------------------------
__global__ __launch_bounds__(256, 4) void k_scores(const int* __restrict__ mask)
{
    extern __shared__ __half sb[];
    unsigned char* Msk = (unsigned char*)sb + MSK_OFF;

    const int b  = blockIdx.x >> 4;
    const int n  = blockIdx.x & 15;
    const int j0 = blockIdx.y * TJ;
    const int jt = blockIdx.y;
    const int i0 = blockIdx.z * TI;
    const int tid  = threadIdx.x;
    const int w    = tid >> 5;
    const int lane = tid & 31;

    const size_t mbase = (size_t)(b * LL + i0) * LL + j0;
#pragma unroll
    for (int t = 0; t < 8; t++) {
        int idx = tid + t * 256;           // 2048 int4
        int j4 = idx & 15, i = idx >> 4;
        int4 m = *(const int4*)&mask[mbase + (size_t)i * LL + j4 * 4];
        unsigned pack = (m.x ? 1u : 0u) | (m.y ? 0x100u : 0u) |
                        (m.z ? 0x10000u : 0u) | (m.w ? 0x1000000u : 0u);
        *(unsigned*)&Msk[i * 64 + j4 * 4] = pack;
    }

    const size_t qbase = ((size_t)(b * NH + n) * LL + i0) * DD;
    const size_t kbase = ((size_t)(b * NH + n) * LL + j0) * DD;
#pragma unroll
    for (int t = 0; t < 4; t++) {
        int idx = tid + t * 256;           // 1024 uint4
        int r = idx >> 3, c8 = idx & 7;
        *(uint4*)&sb[QHI_OFF + r * PCH + c8 * 8] =
            *(const uint4*)&g_qh[qbase + (size_t)r * DD + c8 * 8];
    }
#pragma unroll
    for (int t = 0; t < 2; t++) {
        int idx = tid + t * 256;           // 512 uint4
        int r = idx >> 3, c8 = idx & 7;
        *(uint4*)&sb[KHI_OFF + r * PCH + c8 * 8] =
            *(const uint4*)&g_kh[kbase + (size_t)r * DD + c8 * 8];
    }
    __syncthreads();

    float4 acc[8];
#pragma unroll
    for (int jf = 0; jf < 8; jf++) acc[jf] = make_float4(0.f, 0.f, 0.f, 0.f);

    const int a_row = w * 16 + (lane & 15);
    const int a_kof = (lane >> 4) << 3;
    const int b_row = ((lane >> 4) << 3) + (lane & 7);
    const int b_kof = ((lane >> 3) & 1) << 3;

#pragma unroll
    for (int ks = 0; ks < 4; ks++) {
        const int k0 = ks * 16;
        uint32_t ah[4];
        ldmatrix_x4(ah[0], ah[1], ah[2], ah[3],
                    smem_u32(&sb[QHI_OFF + a_row * PCH + k0 + a_kof]));
#pragma unroll
        for (int jp = 0; jp < 4; jp++) {
            uint32_t bh0, bh1, bh2, bh3;
            ldmatrix_x4(bh0, bh1, bh2, bh3,
                        smem_u32(&sb[KHI_OFF + (jp * 16 + b_row) * PCH + k0 + b_kof]));
            mma_f16(acc[jp * 2],     ah, bh0, bh1);
            mma_f16(acc[jp * 2 + 1], ah, bh2, bh3);
        }
    }

    // ---- epilogue: u = exp(s) (masked -> 0), fp16 store, per-warp row sums ----
    const int qr = lane >> 2, qc = (lane & 3) * 2;
    const int lr0 = w * 16 + qr;
    const int r0g = i0 + lr0;
    const size_t srow0 = ((size_t)(b * NH + n) * LL + r0g) * LL + j0;
    const size_t srow1 = srow0 + (size_t)8 * LL;
    float sum0 = 0.f, sum1 = 0.f;
#pragma unroll
    for (int jf = 0; jf < 8; jf++) {
        const int lj = jf * 8 + qc;
        float4 a = acc[jf];
        unsigned char m0a = Msk[lr0 * 64 + lj],       m0b = Msk[lr0 * 64 + lj + 1];
        unsigned char m1a = Msk[(lr0 + 8) * 64 + lj], m1b = Msk[(lr0 + 8) * 64 + lj + 1];
        float u0x = m0a ? 0.f : __expf(a.x * SCALE);
        float u0y = m0b ? 0.f : __expf(a.y * SCALE);
        float u1x = m1a ? 0.f : __expf(a.z * SCALE);
        float u1y = m1b ? 0.f : __expf(a.w * SCALE);
        *(__half2*)&g_scores[srow0 + lj] = __floats2half2_rn(u0x, u0y);
        *(__half2*)&g_scores[srow1 + lj] = __floats2half2_rn(u1x, u1y);
        sum0 += u0x + u0y;
        sum1 += u1x + u1y;
    }
    sum0 += __shfl_xor_sync(0xffffffffu, sum0, 1);
    sum0 += __shfl_xor_sync(0xffffffffu, sum0, 2);
    sum1 += __shfl_xor_sync(0xffffffffu, sum1, 1);
    sum1 += __shfl_xor_sync(0xffffffffu, sum1, 2);
    if ((lane & 3) == 0) {
        size_t base = (size_t)jt * NROWS + (size_t)(b * NH + n) * LL + r0g;
        g_tl[base] = sum0;
        g_tl[base + 8] = sum1;
    }
}

// ---------------------------------------------------------------------------
// Kernel 2: combine tile sums -> g_c = 1/L.
// ---------------------------------------------------------------------------
__global__ __launch_bounds__(256) void k_comb()
{
    const int r = blockIdx.x * 256 + threadIdx.x;
    float L = 0.f;
#pragma unroll
    for (int t = 0; t < NTJ; t++) L += g_tl[(size_t)t * NROWS + r];
    const int i = r & (LL - 1);
    const int n = (r >> 11) & (NH - 1);
    const int b = r >> 15;
    g_c[((size_t)(b * LL + i)) * NH + n] = 1.f / L;
}

// ---------------------------------------------------------------------------
// Kernel 3: attn output. 512 threads x 3 CTAs/SM (reg-capped at 42).
// p = u * c, transpose [b,n,i,j](fp16) -> [b,i,j,n](f32). 32i x 32j x 16n tile.
// ---------------------------------------------------------------------------
#define RS 545
__global__ __launch_bounds__(512, 3) void k_attn(float* __restrict__ attn)
{
    extern __shared__ float S[];       // 32*RS floats
    __shared__ float Cs[512];          // [32 ii][16 n]
    const int b = blockIdx.z, i0 = blockIdx.y * 32, j0 = blockIdx.x * 32;
    const int tid = threadIdx.x;

    Cs[tid] = g_c[(size_t)(b * LL + i0) * NH + tid];
    __syncthreads();

#pragma unroll
    for (int kk = 0; kk < 4; kk++) {
        int idx = tid + kk * 512;          // 2048 uint4 (8 halves each)
        int c8 = idx & 3, ii = (idx >> 2) & 31, n = idx >> 7;
        uint4 raw = *(const uint4*)&g_scores[
            (((size_t)(b * NH + n)) * LL + i0 + ii) * LL + j0 + c8 * 8];
        const __half2* h2 = (const __half2*)&raw;
        float c = Cs[ii * 16 + n];
        int sbase = ii * 17 + n;
#pragma unroll
        for (int t = 0; t < 4; t++) {
            float2 f = __half22float2(h2[t]);
            int jl = c8 * 8 + t * 2;
            S[jl * RS + sbase] = f.x * c;
            S[(jl + 1) * RS + sbase] = f.y * c;
        }
    }
    __syncthreads();

#pragma unroll
    for (int kk = 0; kk < 8; kk++) {
        int idx = tid + kk * 512;          // 4096 float4
        int n4 = (idx & 3) * 4, jj = (idx >> 2) & 31, ii = idx >> 7;
        const float* s = &S[jj * RS + ii * 17 + n4];
        float4 v = make_float4(s[0], s[1], s[2], s[3]);
        *(float4*)&attn[(((size_t)(b * LL + i0 + ii)) * LL + j0 + jj) * NH + n4] = v;
    }
}

// ---------------------------------------------------------------------------
// Kernel 4: tensor PV, cp.async double-buffered, fp16.
// CTA = (b,n) x 128 i. 8 warps, warp = 16 i x 64 d. ctx = c * (P_f16 @ Vh).
// ---------------------------------------------------------------------------
#define PVB_L 0
#define VVH_L (128 * PCH)
#define ST_ELEMS (128 * PCH + 64 * PCH)         // 13824 halves / stage
#define SMEM4_BYTES (2 * ST_ELEMS * 2)          // 55296 B

__global__ __launch_bounds__(256, 3) void k_pvt(float* __restrict__ ctx)
{
    extern __shared__ __half pb[];

    const int bn = blockIdx.x;           // b*16+n
    const int b = bn >> 4, n = bn & 15;
    const int i0 = blockIdx.y * 128;
    const int tid = threadIdx.x, w = tid >> 5, lane = tid & 31;

    float4 acc[8];
#pragma unroll
    for (int g = 0; g < 8; g++) acc[g] = make_float4(0.f, 0.f, 0.f, 0.f);

    const size_t ubase = ((size_t)bn * LL + i0) * LL;
    const size_t vbase = (size_t)bn * LL * DD;
    const uint32_t pb0 = smem_u32(pb);

    const int a_row = w * 16 + (lane & 15);
    const int a_kof = (lane >> 4) << 3;
    const int v_rof = ((lane >> 3) & 1) * 8 + (lane & 7);
    const int v_cof = (lane >> 4) * 8;

    auto issue = [&](int jt, int stage) {
        const uint32_t dst = pb0 + stage * (ST_ELEMS * 2);
        const int j0 = jt * 64;
        {
            int idx = tid;                 // 512 lines for V (2 per thread)
            int r = idx >> 3, c8 = idx & 7;
            cp_async16(dst + (VVH_L + r * PCH + c8 * 8) * 2,
                       &g_vh[vbase + (size_t)(j0 + r) * DD + c8 * 8]);
            idx = tid + 256;
            r = idx >> 3; c8 = idx & 7;
            cp_async16(dst + (VVH_L + r * PCH + c8 * 8) * 2,
                       &g_vh[vbase + (size_t)(j0 + r) * DD + c8 * 8]);
        }
#pragma unroll
        for (int t = 0; t < 4; t++) {
            int idx = tid + t * 256;       // 1024 lines for u
            int row = idx >> 3, c8 = idx & 7;
            cp_async16(dst + (PVB_L + row * PCH + c8 * 8) * 2,
                       &g_scores[ubase + (size_t)row * LL + j0 + c8 * 8]);
        }
        CP_COMMIT();
    };

    issue(0, 0);

    for (int jt = 0; jt < NTJ; jt++) {
        const int cur = jt & 1;
        if (jt + 1 < NTJ) {
            issue(jt + 1, cur ^ 1);
            CP_WAIT(1);
        } else {
            CP_WAIT(0);
        }
        __syncthreads();

        const __half* buf = pb + cur * ST_ELEMS;
#pragma unroll
        for (int ks = 0; ks < 4; ks++) {
            const int k0 = ks * 16;
            uint32_t ah[4];
            ldmatrix_x4(ah[0], ah[1], ah[2], ah[3],
                        smem_u32(&buf[PVB_L + a_row * PCH + k0 + a_kof]));
#pragma unroll
            for (int ng = 0; ng < 4; ng++) {
                uint32_t bh0, bh1, bh2, bh3;
                const int voff = (k0 + v_rof) * PCH + ng * 16 + v_cof;
                ldmatrix_x4_t(bh0, bh1, bh2, bh3, smem_u32(&buf[VVH_L + voff]));
                mma_f16(acc[ng * 2],     ah, bh0, bh1);
                mma_f16(acc[ng * 2 + 1], ah, bh2, bh3);
            }
        }
        __syncthreads();
    }

    const int r = w * 16 + (lane >> 2);
    const float c0 = g_c[((size_t)(b * LL + i0 + r)) * NH + n];
    const float c1 = g_c[((size_t)(b * LL + i0 + r + 8)) * NH + n];
#pragma unroll
    for (int ng = 0; ng < 8; ng++) {
        int colb = ng * 8 + (lane & 3) * 2;
        size_t g0 = (((size_t)(b * LL + i0 + r)) * NH + n) * DD + colb;
        size_t g1 = (((size_t)(b * LL + i0 + r + 8)) * NH + n) * DD + colb;
        *(float2*)&ctx[g0] = make_float2(acc[ng].x * c0, acc[ng].y * c0);
        *(float2*)&ctx[g1] = make_float2(acc[ng].z * c1, acc[ng].w * c1);
    }
}

// ---------------------------------------------------------------------------
extern "C" void kernel_launch(void* const* d_in, const int* in_sizes, int n_in,
                              void* d_out, int out_size)
{
    const float* q = (const float*)d_in[0];
    const float* k = (const float*)d_in[1];
    const float* v = (const float*)d_in[2];
    const int* mask = (const int*)d_in[3];

    float* ctx  = (float*)d_out;
    float* attn = (float*)d_out + (size_t)BB * LL * NH * DD;

    const int smem_attn = 32 * RS * 4;          // 69760 B
    cudaFuncSetAttribute(k_scores, cudaFuncAttributeMaxDynamicSharedMemorySize, SMEM1_BYTES);
    cudaFuncSetAttribute(k_attn,   cudaFuncAttributeMaxDynamicSharedMemorySize, smem_attn);
    cudaFuncSetAttribute(k_pvt,    cudaFuncAttributeMaxDynamicSharedMemorySize, SMEM4_BYTES);

    k_split<<<(BB * NH * LL * 32) / 256, 256>>>(q, k, v);

    dim3 g1(BB * NH, LL / TJ, LL / TI);
    k_scores<<<g1, 256, SMEM1_BYTES>>>(mask);

    k_comb<<<NROWS / 256, 256>>>();

    dim3 ga(LL / 32, LL / 32, BB);
    k_attn<<<ga, 512, smem_attn>>>(attn);

    dim3 gp(BB * NH, LL / 128);
    k_pvt<<<gp, 256, SMEM4_BYTES>>>(ctx);
}

// round 14
// speedup vs baseline: 1.4602x; 1.4602x over previous
#include <cuda_runtime.h>
#include <cuda_fp16.h>
#include <math_constants.h>
#include <cstdint>

#define BB 2
#define LL 2048
#define NH 16
#define DD 64
#define SCALE 0.125f

#define TI 128
#define TJ 64
#define NTJ (LL / TJ)            // 32 j-tiles
#define NROWS (BB * NH * LL)     // 65536 softmax rows
#define PCH 72                   // smem pitch in 16-bit elems (144B rows -> conflict-free LDSM)

// scores scratch: u = exp(masked scaled score) in fp16, layout [b][n][i][j]
__device__ __half g_scores[(size_t)BB * NH * LL * LL];
// per-(row, j-tile) partial sums of u, layout [jt][b][n][i]
__device__ float g_tl[NTJ * NROWS];
// final per-row 1/sum, layout [b][i][n]
__device__ float g_c[BB * LL * NH];
// fp16 operands, layout [b][n][j][d]
__device__ __half g_qh[(size_t)BB * NH * LL * DD];
__device__ __half g_kh[(size_t)BB * NH * LL * DD];
__device__ __half g_vh[(size_t)BB * NH * LL * DD];

// ---------------- portable tensor helpers (sm_80+) ----------------
__device__ __forceinline__ uint32_t smem_u32(const void* p) {
    uint32_t a;
    asm("{ .reg .u64 t; cvta.to.shared.u64 t, %1; cvt.u32.u64 %0, t; }" : "=r"(a) : "l"(p));
    return a;
}
__device__ __forceinline__ void ldmatrix_x4(uint32_t& r0, uint32_t& r1,
                                            uint32_t& r2, uint32_t& r3, uint32_t addr) {
    asm volatile("ldmatrix.sync.aligned.m8n8.x4.shared.b16 {%0,%1,%2,%3}, [%4];"
                 : "=r"(r0), "=r"(r1), "=r"(r2), "=r"(r3) : "r"(addr));
}
__device__ __forceinline__ void ldmatrix_x4_t(uint32_t& r0, uint32_t& r1,
                                              uint32_t& r2, uint32_t& r3, uint32_t addr) {
    asm volatile("ldmatrix.sync.aligned.m8n8.x4.trans.shared.b16 {%0,%1,%2,%3}, [%4];"
                 : "=r"(r0), "=r"(r1), "=r"(r2), "=r"(r3) : "r"(addr));
}
__device__ __forceinline__ void mma_f16(float4& d, const uint32_t a[4],
                                        uint32_t b0, uint32_t b1) {
    asm volatile(
        "mma.sync.aligned.m16n8k16.row.col.f32.f16.f16.f32 "
        "{%0,%1,%2,%3},{%4,%5,%6,%7},{%8,%9},{%0,%1,%2,%3};"
        : "+f"(d.x), "+f"(d.y), "+f"(d.z), "+f"(d.w)
        : "r"(a[0]), "r"(a[1]), "r"(a[2]), "r"(a[3]), "r"(b0), "r"(b1));
}
__device__ __forceinline__ void cp_async16(uint32_t smem, const void* gmem) {
    asm volatile("cp.async.cg.shared.global [%0], [%1], 16;" :: "r"(smem), "l"(gmem));
}
#define CP_COMMIT() asm volatile("cp.async.commit_group;" ::: "memory")
#define CP_WAIT(n)  asm volatile("cp.async.wait_group %0;" :: "n"(n) : "memory")

// ---------------------------------------------------------------------------
// Kernel 0: cast Q,K,V -> fp16, transpose [b,i,n,d] -> [b,n,i,d].
// ---------------------------------------------------------------------------
__global__ __launch_bounds__(256) void k_split(
    const float* __restrict__ q, const float* __restrict__ k,
    const float* __restrict__ v)
{
    int idx = blockIdx.x * 256 + threadIdx.x;   // BB*NH*LL*32
    int d2 = idx & 31;
    int j  = (idx >> 5) & (LL - 1);
    int n  = (idx >> 16) & 15;
    int b  = idx >> 20;
    size_t src = (((size_t)(b * LL + j)) * NH + n) * DD + d2 * 2;
    size_t dst = (((size_t)(b * NH + n)) * LL + j) * DD + d2 * 2;

    float2 xq = *(const float2*)&q[src];
    float2 xk = *(const float2*)&k[src];
    float2 xv = *(const float2*)&v[src];
    *(__half2*)&g_qh[dst] = __floats2half2_rn(xq.x, xq.y);
    *(__half2*)&g_kh[dst] = __floats2half2_rn(xk.x, xk.y);
    *(__half2*)&g_vh[dst] = __floats2half2_rn(xv.x, xv.y);
}

// smem element offsets for k_scores (16-bit units)
#define QHI_OFF 0
#define KHI_OFF (TI * PCH)
#define MSK_OFF ((TI * PCH + TJ * PCH) * 2)               // byte offset of mask
#define SMEM1_BYTES (MSK_OFF + TI * TJ)                   // 27648 + 8192 = 35840 B

// ---------------------------------------------------------------------------
// Kernel 1: HMMA scores (pure fp16: S = Qh*Kh). CTA = (b,n) x 128i x 64j.
// 8 warps, warp = 16i x 64j. occ=3 (no reg spills; reg cap 85).
// ---------------------------------------------------------------------------
__global__ __launch_bounds__(256, 3) void k_scores(const int* __restrict__ mask)
{
    extern __shared__ __half sb[];
    unsigned char* Msk = (unsigned char*)sb + MSK_OFF;

    const int b  = blockIdx.x >> 4;
    const int n  = blockIdx.x & 15;
    const int j0 = blockIdx.y * TJ;
    const int jt = blockIdx.y;
    const int i0 = blockIdx.z * TI;
    const int tid  = threadIdx.x;
    const int w    = tid >> 5;
    const int lane = tid & 31;

    const size_t mbase = (size_t)(b * LL + i0) * LL + j0;
#pragma unroll
    for (int t = 0; t < 8; t++) {
        int idx = tid + t * 256;           // 2048 int4
        int j4 = idx & 15, i = idx >> 4;
        int4 m = *(const int4*)&mask[mbase + (size_t)i * LL + j4 * 4];
        unsigned pack = (m.x ? 1u : 0u) | (m.y ? 0x100u : 0u) |
                        (m.z ? 0x10000u : 0u) | (m.w ? 0x1000000u : 0u);
        *(unsigned*)&Msk[i * 64 + j4 * 4] = pack;
    }

    const size_t qbase = ((size_t)(b * NH + n) * LL + i0) * DD;
    const size_t kbase = ((size_t)(b * NH + n) * LL + j0) * DD;
#pragma unroll
    for (int t = 0; t < 4; t++) {
        int idx = tid + t * 256;           // 1024 uint4
        int r = idx >> 3, c8 = idx & 7;
        *(uint4*)&sb[QHI_OFF + r * PCH + c8 * 8] =
            *(const uint4*)&g_qh[qbase + (size_t)r * DD + c8 * 8];
    }
#pragma unroll
    for (int t = 0; t < 2; t++) {
        int idx = tid + t * 256;           // 512 uint4
        int r = idx >> 3, c8 = idx & 7;
        *(uint4*)&sb[KHI_OFF + r * PCH + c8 * 8] =
            *(const uint4*)&g_kh[kbase + (size_t)r * DD + c8 * 8];
    }
    __syncthreads();

    float4 acc[8];
#pragma unroll
    for (int jf = 0; jf < 8; jf++) acc[jf] = make_float4(0.f, 0.f, 0.f, 0.f);

    const int a_row = w * 16 + (lane & 15);
    const int a_kof = (lane >> 4) << 3;
    const int b_row = ((lane >> 4) << 3) + (lane & 7);
    const int b_kof = ((lane >> 3) & 1) << 3;

#pragma unroll
    for (int ks = 0; ks < 4; ks++) {
        const int k0 = ks * 16;
        uint32_t ah[4];
        ldmatrix_x4(ah[0], ah[1], ah[2], ah[3],
                    smem_u32(&sb[QHI_OFF + a_row * PCH + k0 + a_kof]));
#pragma unroll
        for (int jp = 0; jp < 4; jp++) {
            uint32_t bh0, bh1, bh2, bh3;
            ldmatrix_x4(bh0, bh1, bh2, bh3,
                        smem_u32(&sb[KHI_OFF + (jp * 16 + b_row) * PCH + k0 + b_kof]));
            mma_f16(acc[jp * 2],     ah, bh0, bh1);
            mma_f16(acc[jp * 2 + 1], ah, bh2, bh3);
        }
    }

    // ---- epilogue: u = exp(s) (masked -> 0), fp16 store, per-warp row sums ----
    const int qr = lane >> 2, qc = (lane & 3) * 2;
    const int lr0 = w * 16 + qr;
    const int r0g = i0 + lr0;
    const size_t srow0 = ((size_t)(b * NH + n) * LL + r0g) * LL + j0;
    const size_t srow1 = srow0 + (size_t)8 * LL;
    float sum0 = 0.f, sum1 = 0.f;
#pragma unroll
    for (int jf = 0; jf < 8; jf++) {
        const int lj = jf * 8 + qc;
        float4 a = acc[jf];
        unsigned char m0a = Msk[lr0 * 64 + lj],       m0b = Msk[lr0 * 64 + lj + 1];
        unsigned char m1a = Msk[(lr0 + 8) * 64 + lj], m1b = Msk[(lr0 + 8) * 64 + lj + 1];
        float u0x = m0a ? 0.f : __expf(a.x * SCALE);
        float u0y = m0b ? 0.f : __expf(a.y * SCALE);
        float u1x = m1a ? 0.f : __expf(a.z * SCALE);
        float u1y = m1b ? 0.f : __expf(a.w * SCALE);
        *(__half2*)&g_scores[srow0 + lj] = __floats2half2_rn(u0x, u0y);
        *(__half2*)&g_scores[srow1 + lj] = __floats2half2_rn(u1x, u1y);
        sum0 += u0x + u0y;
        sum1 += u1x + u1y;
    }
    sum0 += __shfl_xor_sync(0xffffffffu, sum0, 1);
    sum0 += __shfl_xor_sync(0xffffffffu, sum0, 2);
    sum1 += __shfl_xor_sync(0xffffffffu, sum1, 1);
    sum1 += __shfl_xor_sync(0xffffffffu, sum1, 2);
    if ((lane & 3) == 0) {
        size_t base = (size_t)jt * NROWS + (size_t)(b * NH + n) * LL + r0g;
        g_tl[base] = sum0;
        g_tl[base + 8] = sum1;
    }
}

// ---------------------------------------------------------------------------
// Kernel 2: combine tile sums -> g_c = 1/L.
// ---------------------------------------------------------------------------
__global__ __launch_bounds__(256) void k_comb()
{
    const int r = blockIdx.x * 256 + threadIdx.x;
    float L = 0.f;
#pragma unroll
    for (int t = 0; t < NTJ; t++) L += g_tl[(size_t)t * NROWS + r];
    const int i = r & (LL - 1);
    const int n = (r >> 11) & (NH - 1);
    const int b = r >> 15;
    g_c[((size_t)(b * LL + i)) * NH + n] = 1.f / L;
}

// ---------------------------------------------------------------------------
// Kernel 3: attn output. 512 threads x 2 CTAs/SM (round-12 proven config).
// p = u * c, transpose [b,n,i,j](fp16) -> [b,i,j,n](f32). 32i x 32j x 16n tile.
// ---------------------------------------------------------------------------
#define RS 545
__global__ __launch_bounds__(512, 2) void k_attn(float* __restrict__ attn)
{
    extern __shared__ float S[];       // 32*RS floats
    __shared__ float Cs[512];          // [32 ii][16 n]
    const int b = blockIdx.z, i0 = blockIdx.y * 32, j0 = blockIdx.x * 32;
    const int tid = threadIdx.x;

    Cs[tid] = g_c[(size_t)(b * LL + i0) * NH + tid];
    __syncthreads();

#pragma unroll
    for (int kk = 0; kk < 4; kk++) {
        int idx = tid + kk * 512;          // 2048 uint4 (8 halves each)
        int c8 = idx & 3, ii = (idx >> 2) & 31, n = idx >> 7;
        uint4 raw = *(const uint4*)&g_scores[
            (((size_t)(b * NH + n)) * LL + i0 + ii) * LL + j0 + c8 * 8];
        const __half2* h2 = (const __half2*)&raw;
        float c = Cs[ii * 16 + n];
        int sbase = ii * 17 + n;
#pragma unroll
        for (int t = 0; t < 4; t++) {
            float2 f = __half22float2(h2[t]);
            int jl = c8 * 8 + t * 2;
            S[jl * RS + sbase] = f.x * c;
            S[(jl + 1) * RS + sbase] = f.y * c;
        }
    }
    __syncthreads();

#pragma unroll
    for (int kk = 0; kk < 8; kk++) {
        int idx = tid + kk * 512;          // 4096 float4
        int n4 = (idx & 3) * 4, jj = (idx >> 2) & 31, ii = idx >> 7;
        const float* s = &S[jj * RS + ii * 17 + n4];
        float4 v = make_float4(s[0], s[1], s[2], s[3]);
        *(float4*)&attn[(((size_t)(b * LL + i0 + ii)) * LL + j0 + jj) * NH + n4] = v;
    }
}

// ---------------------------------------------------------------------------
// Kernel 4: tensor PV, cp.async double-buffered, fp16.
// CTA = (b,n) x 128 i. 8 warps, warp = 16 i x 64 d. ctx = c * (P_f16 @ Vh).
// ---------------------------------------------------------------------------
#define PVB_L 0
#define VVH_L (128 * PCH)
#define ST_ELEMS (128 * PCH + 64 * PCH)         // 13824 halves / stage
#define SMEM4_BYTES (2 * ST_ELEMS * 2)          // 55296 B

__global__ __launch_bounds__(256, 3) void k_pvt(float* __restrict__ ctx)
{
    extern __shared__ __half pb[];

    const int bn = blockIdx.x;           // b*16+n
    const int b = bn >> 4, n = bn & 15;
    const int i0 = blockIdx.y * 128;
    const int tid = threadIdx.x, w = tid >> 5, lane = tid & 31;

    float4 acc[8];
#pragma unroll
    for (int g = 0; g < 8; g++) acc[g] = make_float4(0.f, 0.f, 0.f, 0.f);

    const size_t ubase = ((size_t)bn * LL + i0) * LL;
    const size_t vbase = (size_t)bn * LL * DD;
    const uint32_t pb0 = smem_u32(pb);

    const int a_row = w * 16 + (lane & 15);
    const int a_kof = (lane >> 4) << 3;
    const int v_rof = ((lane >> 3) & 1) * 8 + (lane & 7);
    const int v_cof = (lane >> 4) * 8;

    auto issue = [&](int jt, int stage) {
        const uint32_t dst = pb0 + stage * (ST_ELEMS * 2);
        const int j0 = jt * 64;
        {
            int idx = tid;                 // 512 lines for V (2 per thread)
            int r = idx >> 3, c8 = idx & 7;
            cp_async16(dst + (VVH_L + r * PCH + c8 * 8) * 2,
                       &g_vh[vbase + (size_t)(j0 + r) * DD + c8 * 8]);
            idx = tid + 256;
            r = idx >> 3; c8 = idx & 7;
            cp_async16(dst + (VVH_L + r * PCH + c8 * 8) * 2,
                       &g_vh[vbase + (size_t)(j0 + r) * DD + c8 * 8]);
        }
#pragma unroll
        for (int t = 0; t < 4; t++) {
            int idx = tid + t * 256;       // 1024 lines for u
            int row = idx >> 3, c8 = idx & 7;
            cp_async16(dst + (PVB_L + row * PCH + c8 * 8) * 2,
                       &g_scores[ubase + (size_t)row * LL + j0 + c8 * 8]);
        }
        CP_COMMIT();
    };

    issue(0, 0);

    for (int jt = 0; jt < NTJ; jt++) {
        const int cur = jt & 1;
        if (jt + 1 < NTJ) {
            issue(jt + 1, cur ^ 1);
            CP_WAIT(1);
        } else {
            CP_WAIT(0);
        }
        __syncthreads();

        const __half* buf = pb + cur * ST_ELEMS;
#pragma unroll
        for (int ks = 0; ks < 4; ks++) {
            const int k0 = ks * 16;
            uint32_t ah[4];
            ldmatrix_x4(ah[0], ah[1], ah[2], ah[3],
                        smem_u32(&buf[PVB_L + a_row * PCH + k0 + a_kof]));
#pragma unroll
            for (int ng = 0; ng < 4; ng++) {
                uint32_t bh0, bh1, bh2, bh3;
                const int voff = (k0 + v_rof) * PCH + ng * 16 + v_cof;
                ldmatrix_x4_t(bh0, bh1, bh2, bh3, smem_u32(&buf[VVH_L + voff]));
                mma_f16(acc[ng * 2],     ah, bh0, bh1);
                mma_f16(acc[ng * 2 + 1], ah, bh2, bh3);
            }
        }
        __syncthreads();
    }

    const int r = w * 16 + (lane >> 2);
    const float c0 = g_c[((size_t)(b * LL + i0 + r)) * NH + n];
    const float c1 = g_c[((size_t)(b * LL + i0 + r + 8)) * NH + n];
#pragma unroll
    for (int ng = 0; ng < 8; ng++) {
        int colb = ng * 8 + (lane & 3) * 2;
        size_t g0 = (((size_t)(b * LL + i0 + r)) * NH + n) * DD + colb;
        size_t g1 = (((size_t)(b * LL + i0 + r + 8)) * NH + n) * DD + colb;
        *(float2*)&ctx[g0] = make_float2(acc[ng].x * c0, acc[ng].y * c0);
        *(float2*)&ctx[g1] = make_float2(acc[ng].z * c1, acc[ng].w * c1);
    }
}

// ---------------------------------------------------------------------------
extern "C" void kernel_launch(void* const* d_in, const int* in_sizes, int n_in,
                              void* d_out, int out_size)
{
    const float* q = (const float*)d_in[0];
    const float* k = (const float*)d_in[1];
    const float* v = (const float*)d_in[2];
    const int* mask = (const int*)d_in[3];

    float* ctx  = (float*)d_out;
    float* attn = (float*)d_out + (size_t)BB * LL * NH * DD;

    const int smem_attn = 32 * RS * 4;          // 69760 B
    cudaFuncSetAttribute(k_scores, cudaFuncAttributeMaxDynamicSharedMemorySize, SMEM1_BYTES);
    cudaFuncSetAttribute(k_attn,   cudaFuncAttributeMaxDynamicSharedMemorySize, smem_attn);
    cudaFuncSetAttribute(k_pvt,    cudaFuncAttributeMaxDynamicSharedMemorySize, SMEM4_BYTES);

    k_split<<<(BB * NH * LL * 32) / 256, 256>>>(q, k, v);

    dim3 g1(BB * NH, LL / TJ, LL / TI);
    k_scores<<<g1, 256, SMEM1_BYTES>>>(mask);

    k_comb<<<NROWS / 256, 256>>>();

    dim3 ga(LL / 32, LL / 32, BB);
    k_attn<<<ga, 512, smem_attn>>>(attn);

    dim3 gp(BB * NH, LL / 128);
    k_pvt<<<gp, 256, SMEM4_BYTES>>>(ctx);
}

// round 15
// speedup vs baseline: 1.5633x; 1.0706x over previous
#include <cuda_runtime.h>
#include <cuda_fp16.h>
#include <math_constants.h>
#include <cstdint>

#define BB 2
#define LL 2048
#define NH 16
#define DD 64
#define SCALE 0.125f

#define TI 128
#define TJ 64
#define NTJ (LL / TJ)            // 32 j-tiles
#define NROWS (BB * NH * LL)     // 65536 softmax rows
#define PCH 72                   // smem pitch in 16-bit elems (144B rows -> conflict-free LDSM)

// scores scratch: u = exp(masked scaled score) in fp16, layout [b][n][i][j]
__device__ __half g_scores[(size_t)BB * NH * LL * LL];
// per-(row, j-tile) partial sums of u, layout [jt][b][n][i]
__device__ float g_tl[NTJ * NROWS];
// final per-row 1/sum, layout [b][i][n]
__device__ float g_c[BB * LL * NH];
// fp16 operands, layout [b][n][j][d]
__device__ __half g_qh[(size_t)BB * NH * LL * DD];
__device__ __half g_kh[(size_t)BB * NH * LL * DD];
__device__ __half g_vh[(size_t)BB * NH * LL * DD];
// mask packed to bytes, layout [b][i][j]
__device__ unsigned char g_mask8[(size_t)BB * LL * LL];

// ---------------- portable tensor helpers (sm_80+) ----------------
__device__ __forceinline__ uint32_t smem_u32(const void* p) {
    uint32_t a;
    asm("{ .reg .u64 t; cvta.to.shared.u64 t, %1; cvt.u32.u64 %0, t; }" : "=r"(a) : "l"(p));
    return a;
}
__device__ __forceinline__ void ldmatrix_x4(uint32_t& r0, uint32_t& r1,
                                            uint32_t& r2, uint32_t& r3, uint32_t addr) {
    asm volatile("ldmatrix.sync.aligned.m8n8.x4.shared.b16 {%0,%1,%2,%3}, [%4];"
                 : "=r"(r0), "=r"(r1), "=r"(r2), "=r"(r3) : "r"(addr));
}
__device__ __forceinline__ void ldmatrix_x4_t(uint32_t& r0, uint32_t& r1,
                                              uint32_t& r2, uint32_t& r3, uint32_t addr) {
    asm volatile("ldmatrix.sync.aligned.m8n8.x4.trans.shared.b16 {%0,%1,%2,%3}, [%4];"
                 : "=r"(r0), "=r"(r1), "=r"(r2), "=r"(r3) : "r"(addr));
}
__device__ __forceinline__ void mma_f16(float4& d, const uint32_t a[4],
                                        uint32_t b0, uint32_t b1) {
    asm volatile(
        "mma.sync.aligned.m16n8k16.row.col.f32.f16.f16.f32 "
        "{%0,%1,%2,%3},{%4,%5,%6,%7},{%8,%9},{%0,%1,%2,%3};"
        : "+f"(d.x), "+f"(d.y), "+f"(d.z), "+f"(d.w)
        : "r"(a[0]), "r"(a[1]), "r"(a[2]), "r"(a[3]), "r"(b0), "r"(b1));
}
__device__ __forceinline__ void cp_async16(uint32_t smem, const void* gmem) {
    asm volatile("cp.async.cg.shared.global [%0], [%1], 16;" :: "r"(smem), "l"(gmem));
}
#define CP_COMMIT() asm volatile("cp.async.commit_group;" ::: "memory")
#define CP_WAIT(n)  asm volatile("cp.async.wait_group %0;" :: "n"(n) : "memory")

// ---------------------------------------------------------------------------
// Kernel -1: pack mask int32 -> bytes. 16 elements per thread, both sides coalesced.
// ---------------------------------------------------------------------------
__global__ __launch_bounds__(256) void k_mask(const int* __restrict__ mask)
{
    size_t base = ((size_t)blockIdx.x * 256 + threadIdx.x) * 16;
    int4 a = *(const int4*)&mask[base];
    int4 b = *(const int4*)&mask[base + 4];
    int4 c = *(const int4*)&mask[base + 8];
    int4 d = *(const int4*)&mask[base + 12];
    uint4 o;
    o.x = (a.x ? 1u : 0u) | (a.y ? 0x100u : 0u) | (a.z ? 0x10000u : 0u) | (a.w ? 0x1000000u : 0u);
    o.y = (b.x ? 1u : 0u) | (b.y ? 0x100u : 0u) | (b.z ? 0x10000u : 0u) | (b.w ? 0x1000000u : 0u);
    o.z = (c.x ? 1u : 0u) | (c.y ? 0x100u : 0u) | (c.z ? 0x10000u : 0u) | (c.w ? 0x1000000u : 0u);
    o.w = (d.x ? 1u : 0u) | (d.y ? 0x100u : 0u) | (d.z ? 0x10000u : 0u) | (d.w ? 0x1000000u : 0u);
    *(uint4*)&g_mask8[base] = o;
}

// ---------------------------------------------------------------------------
// Kernel 0: cast Q,K,V -> fp16, transpose [b,i,n,d] -> [b,n,i,d].
// ---------------------------------------------------------------------------
__global__ __launch_bounds__(256) void k_split(
    const float* __restrict__ q, const float* __restrict__ k,
    const float* __restrict__ v)
{
    int idx = blockIdx.x * 256 + threadIdx.x;   // BB*NH*LL*32
    int d2 = idx & 31;
    int j  = (idx >> 5) & (LL - 1);
    int n  = (idx >> 16) & 15;
    int b  = idx >> 20;
    size_t src = (((size_t)(b * LL + j)) * NH + n) * DD + d2 * 2;
    size_t dst = (((size_t)(b * NH + n)) * LL + j) * DD + d2 * 2;

    float2 xq = *(const float2*)&q[src];
    float2 xk = *(const float2*)&k[src];
    float2 xv = *(const float2*)&v[src];
    *(__half2*)&g_qh[dst] = __floats2half2_rn(xq.x, xq.y);
    *(__half2*)&g_kh[dst] = __floats2half2_rn(xk.x, xk.y);
    *(__half2*)&g_vh[dst] = __floats2half2_rn(xv.x, xv.y);
}

// smem element offsets for k_scores (16-bit units)
#define QHI_OFF 0
#define KHI_OFF (TI * PCH)
#define MSK_OFF ((TI * PCH + TJ * PCH) * 2)               // byte offset of mask
#define SMEM1_BYTES (MSK_OFF + TI * TJ)                   // 27648 + 8192 = 35840 B

// ---------------------------------------------------------------------------
// Kernel 1: HMMA scores (pure fp16: S = Qh*Kh). CTA = (b,n) x 128i x 64j.
// 8 warps, warp = 16i x 64j. Byte-mask from g_mask8; u staged in smem
// (pitch 72: conflict-free) for STG.128-coalesced output.
// ---------------------------------------------------------------------------
__global__ __launch_bounds__(256, 3) void k_scores()
{
    extern __shared__ __half sb[];
    unsigned char* Msk = (unsigned char*)sb + MSK_OFF;

    const int b  = blockIdx.x >> 4;
    const int n  = blockIdx.x & 15;
    const int j0 = blockIdx.y * TJ;
    const int jt = blockIdx.y;
    const int i0 = blockIdx.z * TI;
    const int tid  = threadIdx.x;
    const int w    = tid >> 5;
    const int lane = tid & 31;

    // ---- prefetch packed mask tile 128x64 bytes (512 uint4) ----
    const size_t mbase8 = (size_t)(b * LL + i0) * LL + j0;
#pragma unroll
    for (int t = 0; t < 2; t++) {
        int idx = tid + t * 256;
        int i = idx >> 2, c = idx & 3;
        *(uint4*)&Msk[i * 64 + c * 16] =
            *(const uint4*)&g_mask8[mbase8 + (size_t)i * LL + c * 16];
    }

    const size_t qbase = ((size_t)(b * NH + n) * LL + i0) * DD;
    const size_t kbase = ((size_t)(b * NH + n) * LL + j0) * DD;
#pragma unroll
    for (int t = 0; t < 4; t++) {
        int idx = tid + t * 256;           // 1024 uint4
        int r = idx >> 3, c8 = idx & 7;
        *(uint4*)&sb[QHI_OFF + r * PCH + c8 * 8] =
            *(const uint4*)&g_qh[qbase + (size_t)r * DD + c8 * 8];
    }
#pragma unroll
    for (int t = 0; t < 2; t++) {
        int idx = tid + t * 256;           // 512 uint4
        int r = idx >> 3, c8 = idx & 7;
        *(uint4*)&sb[KHI_OFF + r * PCH + c8 * 8] =
            *(const uint4*)&g_kh[kbase + (size_t)r * DD + c8 * 8];
    }
    __syncthreads();

    float4 acc[8];
#pragma unroll
    for (int jf = 0; jf < 8; jf++) acc[jf] = make_float4(0.f, 0.f, 0.f, 0.f);

    const int a_row = w * 16 + (lane & 15);
    const int a_kof = (lane >> 4) << 3;
    const int b_row = ((lane >> 4) << 3) + (lane & 7);
    const int b_kof = ((lane >> 3) & 1) << 3;

#pragma unroll
    for (int ks = 0; ks < 4; ks++) {
        const int k0 = ks * 16;
        uint32_t ah[4];
        ldmatrix_x4(ah[0], ah[1], ah[2], ah[3],
                    smem_u32(&sb[QHI_OFF + a_row * PCH + k0 + a_kof]));
#pragma unroll
        for (int jp = 0; jp < 4; jp++) {
            uint32_t bh0, bh1, bh2, bh3;
            ldmatrix_x4(bh0, bh1, bh2, bh3,
                        smem_u32(&sb[KHI_OFF + (jp * 16 + b_row) * PCH + k0 + b_kof]));
            mma_f16(acc[jp * 2],     ah, bh0, bh1);
            mma_f16(acc[jp * 2 + 1], ah, bh2, bh3);
        }
    }

    // ---- epilogue: u = exp(s) (masked -> 0), stage in smem, row sums ----
    __syncthreads();                       // Q/K region dead; reuse as Us
    __half* Us = sb;                       // [128 rows][pitch 72]

    const int qr = lane >> 2, qc = (lane & 3) * 2;
    const int lr0 = w * 16 + qr;           // local row (second: +8)
    const int r0g = i0 + lr0;
    float sum0 = 0.f, sum1 = 0.f;
#pragma unroll
    for (int jf = 0; jf < 8; jf++) {
        const int lj = jf * 8 + qc;
        float4 a = acc[jf];
        unsigned char m0a = Msk[lr0 * 64 + lj],       m0b = Msk[lr0 * 64 + lj + 1];
        unsigned char m1a = Msk[(lr0 + 8) * 64 + lj], m1b = Msk[(lr0 + 8) * 64 + lj + 1];
        float u0x = m0a ? 0.f : __expf(a.x * SCALE);
        float u0y = m0b ? 0.f : __expf(a.y * SCALE);
        float u1x = m1a ? 0.f : __expf(a.z * SCALE);
        float u1y = m1b ? 0.f : __expf(a.w * SCALE);
        *(__half2*)&Us[lr0 * PCH + lj]       = __floats2half2_rn(u0x, u0y);
        *(__half2*)&Us[(lr0 + 8) * PCH + lj] = __floats2half2_rn(u1x, u1y);
        sum0 += u0x + u0y;
        sum1 += u1x + u1y;
    }
    sum0 += __shfl_xor_sync(0xffffffffu, sum0, 1);
    sum0 += __shfl_xor_sync(0xffffffffu, sum0, 2);
    sum1 += __shfl_xor_sync(0xffffffffu, sum1, 1);
    sum1 += __shfl_xor_sync(0xffffffffu, sum1, 2);
    if ((lane & 3) == 0) {
        size_t base = (size_t)jt * NROWS + (size_t)(b * NH + n) * LL + r0g;
        g_tl[base] = sum0;
        g_tl[base + 8] = sum1;
    }
    __syncthreads();

    // ---- coalesced bulk store: 1024 uint4 (STG.128) ----
    const size_t srowbase = ((size_t)(b * NH + n) * LL + i0) * LL + j0;
#pragma unroll
    for (int t = 0; t < 4; t++) {
        int idx = tid + t * 256;
        int row = idx >> 3, c8 = idx & 7;
        *(uint4*)&g_scores[srowbase + (size_t)row * LL + c8 * 8] =
            *(const uint4*)&Us[row * PCH + c8 * 8];
    }
}

// ---------------------------------------------------------------------------
// Kernel 2: combine tile sums -> g_c = 1/L.
// ---------------------------------------------------------------------------
__global__ __launch_bounds__(256) void k_comb()
{
    const int r = blockIdx.x * 256 + threadIdx.x;
    float L = 0.f;
#pragma unroll
    for (int t = 0; t < NTJ; t++) L += g_tl[(size_t)t * NROWS + r];
    const int i = r & (LL - 1);
    const int n = (r >> 11) & (NH - 1);
    const int b = r >> 15;
    g_c[((size_t)(b * LL + i)) * NH + n] = 1.f / L;
}

// ---------------------------------------------------------------------------
// Kernel 3: attn output. 512 threads x 2 CTAs/SM (proven config, 60 regs).
// p = u * c, transpose [b,n,i,j](fp16) -> [b,i,j,n](f32). 32i x 32j x 16n tile.
// ---------------------------------------------------------------------------
#define RS 545
__global__ __launch_bounds__(512, 2) void k_attn(float* __restrict__ attn)
{
    extern __shared__ float S[];       // 32*RS floats
    __shared__ float Cs[512];          // [32 ii][16 n]
    const int b = blockIdx.z, i0 = blockIdx.y * 32, j0 = blockIdx.x * 32;
    const int tid = threadIdx.x;

    Cs[tid] = g_c[(size_t)(b * LL + i0) * NH + tid];
    __syncthreads();

#pragma unroll
    for (int kk = 0; kk < 4; kk++) {
        int idx = tid + kk * 512;          // 2048 uint4 (8 halves each)
        int c8 = idx & 3, ii = (idx >> 2) & 31, n = idx >> 7;
        uint4 raw = *(const uint4*)&g_scores[
            (((size_t)(b * NH + n)) * LL + i0 + ii) * LL + j0 + c8 * 8];
        const __half2* h2 = (const __half2*)&raw;
        float c = Cs[ii * 16 + n];
        int sbase = ii * 17 + n;
#pragma unroll
        for (int t = 0; t < 4; t++) {
            float2 f = __half22float2(h2[t]);
            int jl = c8 * 8 + t * 2;
            S[jl * RS + sbase] = f.x * c;
            S[(jl + 1) * RS + sbase] = f.y * c;
        }
    }
    __syncthreads();

#pragma unroll
    for (int kk = 0; kk < 8; kk++) {
        int idx = tid + kk * 512;          // 4096 float4
        int n4 = (idx & 3) * 4, jj = (idx >> 2) & 31, ii = idx >> 7;
        const float* s = &S[jj * RS + ii * 17 + n4];
        float4 v = make_float4(s[0], s[1], s[2], s[3]);
        *(float4*)&attn[(((size_t)(b * LL + i0 + ii)) * LL + j0 + jj) * NH + n4] = v;
    }
}

// ---------------------------------------------------------------------------
// Kernel 4: tensor PV, cp.async double-buffered, fp16.
// CTA = (b,n) x 128 i. 8 warps, warp = 16 i x 64 d. ctx = c * (P_f16 @ Vh).
// ---------------------------------------------------------------------------
#define PVB_L 0
#define VVH_L (128 * PCH)
#define ST_ELEMS (128 * PCH + 64 * PCH)         // 13824 halves / stage
#define SMEM4_BYTES (2 * ST_ELEMS * 2)          // 55296 B

__global__ __launch_bounds__(256, 3) void k_pvt(float* __restrict__ ctx)
{
    extern __shared__ __half pb[];

    const int bn = blockIdx.x;           // b*16+n
    const int b = bn >> 4, n = bn & 15;
    const int i0 = blockIdx.y * 128;
    const int tid = threadIdx.x, w = tid >> 5, lane = tid & 31;

    float4 acc[8];
#pragma unroll
    for (int g = 0; g < 8; g++) acc[g] = make_float4(0.f, 0.f, 0.f, 0.f);

    const size_t ubase = ((size_t)bn * LL + i0) * LL;
    const size_t vbase = (size_t)bn * LL * DD;
    const uint32_t pb0 = smem_u32(pb);

    const int a_row = w * 16 + (lane & 15);
    const int a_kof = (lane >> 4) << 3;
    const int v_rof = ((lane >> 3) & 1) * 8 + (lane & 7);
    const int v_cof = (lane >> 4) * 8;

    auto issue = [&](int jt, int stage) {
        const uint32_t dst = pb0 + stage * (ST_ELEMS * 2);
        const int j0 = jt * 64;
        {
            int idx = tid;                 // 512 lines for V (2 per thread)
            int r = idx >> 3, c8 = idx & 7;
            cp_async16(dst + (VVH_L + r * PCH + c8 * 8) * 2,
                       &g_vh[vbase + (size_t)(j0 + r) * DD + c8 * 8]);
            idx = tid + 256;
            r = idx >> 3; c8 = idx & 7;
            cp_async16(dst + (VVH_L + r * PCH + c8 * 8) * 2,
                       &g_vh[vbase + (size_t)(j0 + r) * DD + c8 * 8]);
        }
#pragma unroll
        for (int t = 0; t < 4; t++) {
            int idx = tid + t * 256;       // 1024 lines for u
            int row = idx >> 3, c8 = idx & 7;
            cp_async16(dst + (PVB_L + row * PCH + c8 * 8) * 2,
                       &g_scores[ubase + (size_t)row * LL + j0 + c8 * 8]);
        }
        CP_COMMIT();
    };

    issue(0, 0);

    for (int jt = 0; jt < NTJ; jt++) {
        const int cur = jt & 1;
        if (jt + 1 < NTJ) {
            issue(jt + 1, cur ^ 1);
            CP_WAIT(1);
        } else {
            CP_WAIT(0);
        }
        __syncthreads();

        const __half* buf = pb + cur * ST_ELEMS;
#pragma unroll
        for (int ks = 0; ks < 4; ks++) {
            const int k0 = ks * 16;
            uint32_t ah[4];
            ldmatrix_x4(ah[0], ah[1], ah[2], ah[3],
                        smem_u32(&buf[PVB_L + a_row * PCH + k0 + a_kof]));
#pragma unroll
            for (int ng = 0; ng < 4; ng++) {
                uint32_t bh0, bh1, bh2, bh3;
                const int voff = (k0 + v_rof) * PCH + ng * 16 + v_cof;
                ldmatrix_x4_t(bh0, bh1, bh2, bh3, smem_u32(&buf[VVH_L + voff]));
                mma_f16(acc[ng * 2],     ah, bh0, bh1);
                mma_f16(acc[ng * 2 + 1], ah, bh2, bh3);
            }
        }
        __syncthreads();
    }

    const int r = w * 16 + (lane >> 2);
    const float c0 = g_c[((size_t)(b * LL + i0 + r)) * NH + n];
    const float c1 = g_c[((size_t)(b * LL + i0 + r + 8)) * NH + n];
#pragma unroll
    for (int ng = 0; ng < 8; ng++) {
        int colb = ng * 8 + (lane & 3) * 2;
        size_t g0 = (((size_t)(b * LL + i0 + r)) * NH + n) * DD + colb;
        size_t g1 = (((size_t)(b * LL + i0 + r + 8)) * NH + n) * DD + colb;
        *(float2*)&ctx[g0] = make_float2(acc[ng].x * c0, acc[ng].y * c0);
        *(float2*)&ctx[g1] = make_float2(acc[ng].z * c1, acc[ng].w * c1);
    }
}

// ---------------------------------------------------------------------------
extern "C" void kernel_launch(void* const* d_in, const int* in_sizes, int n_in,
                              void* d_out, int out_size)
{
    const float* q = (const float*)d_in[0];
    const float* k = (const float*)d_in[1];
    const float* v = (const float*)d_in[2];
    const int* mask = (const int*)d_in[3];

    float* ctx  = (float*)d_out;
    float* attn = (float*)d_out + (size_t)BB * LL * NH * DD;

    const int smem_attn = 32 * RS * 4;          // 69760 B
    cudaFuncSetAttribute(k_scores, cudaFuncAttributeMaxDynamicSharedMemorySize, SMEM1_BYTES);
    cudaFuncSetAttribute(k_attn,   cudaFuncAttributeMaxDynamicSharedMemorySize, smem_attn);
    cudaFuncSetAttribute(k_pvt,    cudaFuncAttributeMaxDynamicSharedMemorySize, SMEM4_BYTES);

    k_mask<<<(BB * LL * LL) / (16 * 256), 256>>>(mask);

    k_split<<<(BB * NH * LL * 32) / 256, 256>>>(q, k, v);

    dim3 g1(BB * NH, LL / TJ, LL / TI);
    k_scores<<<g1, 256, SMEM1_BYTES>>>();

    k_comb<<<NROWS / 256, 256>>>();

    dim3 ga(LL / 32, LL / 32, BB);
    k_attn<<<ga, 512, smem_attn>>>(attn);

    dim3 gp(BB * NH, LL / 128);
    k_pvt<<<gp, 256, SMEM4_BYTES>>>(ctx);
}

// round 16
// speedup vs baseline: 1.6783x; 1.0736x over previous
#include <cuda_runtime.h>
#include <cuda_fp16.h>
#include <math_constants.h>
#include <cstdint>

#define BB 2
#define LL 2048
#define NH 16
#define DD 64
#define SCALE 0.125f

#define TI 128
#define TJ 64
#define NTJ (LL / TJ)            // 32 j-tiles
#define NROWS (BB * NH * LL)     // 65536 softmax rows
#define PCH 72                   // smem pitch in 16-bit elems (144B rows -> conflict-free LDSM)

// scores scratch: u = exp(masked scaled score) in fp16, layout [b][n][i][j]
__device__ __half g_scores[(size_t)BB * NH * LL * LL];
// per-(row, j-tile) partial sums of u, layout [jt][b][n][i]
__device__ float g_tl[NTJ * NROWS];
// final per-row 1/sum, layout [b][i][n]
__device__ float g_c[BB * LL * NH];
// fp16 operands, layout [b][n][j][d]
__device__ __half g_qh[(size_t)BB * NH * LL * DD];
__device__ __half g_kh[(size_t)BB * NH * LL * DD];
__device__ __half g_vh[(size_t)BB * NH * LL * DD];
// mask packed to bytes, layout [b][i][j]
__device__ unsigned char g_mask8[(size_t)BB * LL * LL];

// ---------------- portable tensor helpers (sm_80+) ----------------
__device__ __forceinline__ uint32_t smem_u32(const void* p) {
    uint32_t a;
    asm("{ .reg .u64 t; cvta.to.shared.u64 t, %1; cvt.u32.u64 %0, t; }" : "=r"(a) : "l"(p));
    return a;
}
__device__ __forceinline__ void ldmatrix_x4(uint32_t& r0, uint32_t& r1,
                                            uint32_t& r2, uint32_t& r3, uint32_t addr) {
    asm volatile("ldmatrix.sync.aligned.m8n8.x4.shared.b16 {%0,%1,%2,%3}, [%4];"
                 : "=r"(r0), "=r"(r1), "=r"(r2), "=r"(r3) : "r"(addr));
}
__device__ __forceinline__ void ldmatrix_x4_t(uint32_t& r0, uint32_t& r1,
                                              uint32_t& r2, uint32_t& r3, uint32_t addr) {
    asm volatile("ldmatrix.sync.aligned.m8n8.x4.trans.shared.b16 {%0,%1,%2,%3}, [%4];"
                 : "=r"(r0), "=r"(r1), "=r"(r2), "=r"(r3) : "r"(addr));
}
__device__ __forceinline__ void mma_f16(float4& d, const uint32_t a[4],
                                        uint32_t b0, uint32_t b1) {
    asm volatile(
        "mma.sync.aligned.m16n8k16.row.col.f32.f16.f16.f32 "
        "{%0,%1,%2,%3},{%4,%5,%6,%7},{%8,%9},{%0,%1,%2,%3};"
        : "+f"(d.x), "+f"(d.y), "+f"(d.z), "+f"(d.w)
        : "r"(a[0]), "r"(a[1]), "r"(a[2]), "r"(a[3]), "r"(b0), "r"(b1));
}
__device__ __forceinline__ void cp_async16(uint32_t smem, const void* gmem) {
    asm volatile("cp.async.cg.shared.global [%0], [%1], 16;" :: "r"(smem), "l"(gmem));
}
#define CP_COMMIT() asm volatile("cp.async.commit_group;" ::: "memory")
#define CP_WAIT(n)  asm volatile("cp.async.wait_group %0;" :: "n"(n) : "memory")

// ---------------------------------------------------------------------------
// Kernel 0: fused prep. CTAs [0,2048): pack mask int32 -> bytes.
//           CTAs [2048,10240): cast Q,K,V -> fp16, [b,i,n,d] -> [b,n,i,d].
// ---------------------------------------------------------------------------
#define MASK_CTAS 2048
__global__ __launch_bounds__(256) void k_prep(
    const float* __restrict__ q, const float* __restrict__ k,
    const float* __restrict__ v, const int* __restrict__ mask)
{
    if (blockIdx.x < MASK_CTAS) {
        size_t base = ((size_t)blockIdx.x * 256 + threadIdx.x) * 16;
        int4 a = *(const int4*)&mask[base];
        int4 b = *(const int4*)&mask[base + 4];
        int4 c = *(const int4*)&mask[base + 8];
        int4 d = *(const int4*)&mask[base + 12];
        uint4 o;
        o.x = (a.x ? 1u : 0u) | (a.y ? 0x100u : 0u) | (a.z ? 0x10000u : 0u) | (a.w ? 0x1000000u : 0u);
        o.y = (b.x ? 1u : 0u) | (b.y ? 0x100u : 0u) | (b.z ? 0x10000u : 0u) | (b.w ? 0x1000000u : 0u);
        o.z = (c.x ? 1u : 0u) | (c.y ? 0x100u : 0u) | (c.z ? 0x10000u : 0u) | (c.w ? 0x1000000u : 0u);
        o.w = (d.x ? 1u : 0u) | (d.y ? 0x100u : 0u) | (d.z ? 0x10000u : 0u) | (d.w ? 0x1000000u : 0u);
        *(uint4*)&g_mask8[base] = o;
    } else {
        int idx = (blockIdx.x - MASK_CTAS) * 256 + threadIdx.x;   // BB*NH*LL*32
        int d2 = idx & 31;
        int j  = (idx >> 5) & (LL - 1);
        int n  = (idx >> 16) & 15;
        int b  = idx >> 20;
        size_t src = (((size_t)(b * LL + j)) * NH + n) * DD + d2 * 2;
        size_t dst = (((size_t)(b * NH + n)) * LL + j) * DD + d2 * 2;
        float2 xq = *(const float2*)&q[src];
        float2 xk = *(const float2*)&k[src];
        float2 xv = *(const float2*)&v[src];
        *(__half2*)&g_qh[dst] = __floats2half2_rn(xq.x, xq.y);
        *(__half2*)&g_kh[dst] = __floats2half2_rn(xk.x, xk.y);
        *(__half2*)&g_vh[dst] = __floats2half2_rn(xv.x, xv.y);
    }
}

// smem element offsets for k_scores (16-bit units)
#define QHI_OFF 0
#define KHI_OFF (TI * PCH)
#define MSK_OFF ((TI * PCH + TJ * PCH) * 2)               // byte offset of mask
#define SMEM1_BYTES (MSK_OFF + TI * TJ)                   // 27648 + 8192 = 35840 B

// ---------------------------------------------------------------------------
// Kernel 1: HMMA scores (pure fp16: S = Qh*Kh). CTA = (b,n) x 128i x 64j.
// 8 warps, warp = 16i x 64j. Byte-mask from g_mask8; u staged in smem
// (pitch 72: conflict-free) for STG.128-coalesced output.
// ---------------------------------------------------------------------------
__global__ __launch_bounds__(256, 3) void k_scores()
{
    extern __shared__ __half sb[];
    unsigned char* Msk = (unsigned char*)sb + MSK_OFF;

    const int b  = blockIdx.x >> 4;
    const int n  = blockIdx.x & 15;
    const int j0 = blockIdx.y * TJ;
    const int jt = blockIdx.y;
    const int i0 = blockIdx.z * TI;
    const int tid  = threadIdx.x;
    const int w    = tid >> 5;
    const int lane = tid & 31;

    // ---- prefetch packed mask tile 128x64 bytes (512 uint4) ----
    const size_t mbase8 = (size_t)(b * LL + i0) * LL + j0;
#pragma unroll
    for (int t = 0; t < 2; t++) {
        int idx = tid + t * 256;
        int i = idx >> 2, c = idx & 3;
        *(uint4*)&Msk[i * 64 + c * 16] =
            *(const uint4*)&g_mask8[mbase8 + (size_t)i * LL + c * 16];
    }

    const size_t qbase = ((size_t)(b * NH + n) * LL + i0) * DD;
    const size_t kbase = ((size_t)(b * NH + n) * LL + j0) * DD;
#pragma unroll
    for (int t = 0; t < 4; t++) {
        int idx = tid + t * 256;           // 1024 uint4
        int r = idx >> 3, c8 = idx & 7;
        *(uint4*)&sb[QHI_OFF + r * PCH + c8 * 8] =
            *(const uint4*)&g_qh[qbase + (size_t)r * DD + c8 * 8];
    }
#pragma unroll
    for (int t = 0; t < 2; t++) {
        int idx = tid + t * 256;           // 512 uint4
        int r = idx >> 3, c8 = idx & 7;
        *(uint4*)&sb[KHI_OFF + r * PCH + c8 * 8] =
            *(const uint4*)&g_kh[kbase + (size_t)r * DD + c8 * 8];
    }
    __syncthreads();

    float4 acc[8];
#pragma unroll
    for (int jf = 0; jf < 8; jf++) acc[jf] = make_float4(0.f, 0.f, 0.f, 0.f);

    const int a_row = w * 16 + (lane & 15);
    const int a_kof = (lane >> 4) << 3;
    const int b_row = ((lane >> 4) << 3) + (lane & 7);
    const int b_kof = ((lane >> 3) & 1) << 3;

#pragma unroll
    for (int ks = 0; ks < 4; ks++) {
        const int k0 = ks * 16;
        uint32_t ah[4];
        ldmatrix_x4(ah[0], ah[1], ah[2], ah[3],
                    smem_u32(&sb[QHI_OFF + a_row * PCH + k0 + a_kof]));
#pragma unroll
        for (int jp = 0; jp < 4; jp++) {
            uint32_t bh0, bh1, bh2, bh3;
            ldmatrix_x4(bh0, bh1, bh2, bh3,
                        smem_u32(&sb[KHI_OFF + (jp * 16 + b_row) * PCH + k0 + b_kof]));
            mma_f16(acc[jp * 2],     ah, bh0, bh1);
            mma_f16(acc[jp * 2 + 1], ah, bh2, bh3);
        }
    }

    // ---- epilogue: u = exp(s) (masked -> 0), stage in smem, row sums ----
    __syncthreads();                       // Q/K region dead; reuse as Us
    __half* Us = sb;                       // [128 rows][pitch 72]

    const int qr = lane >> 2, qc = (lane & 3) * 2;
    const int lr0 = w * 16 + qr;           // local row (second: +8)
    const int r0g = i0 + lr0;
    float sum0 = 0.f, sum1 = 0.f;
#pragma unroll
    for (int jf = 0; jf < 8; jf++) {
        const int lj = jf * 8 + qc;
        float4 a = acc[jf];
        unsigned char m0a = Msk[lr0 * 64 + lj],       m0b = Msk[lr0 * 64 + lj + 1];
        unsigned char m1a = Msk[(lr0 + 8) * 64 + lj], m1b = Msk[(lr0 + 8) * 64 + lj + 1];
        float u0x = m0a ? 0.f : __expf(a.x * SCALE);
        float u0y = m0b ? 0.f : __expf(a.y * SCALE);
        float u1x = m1a ? 0.f : __expf(a.z * SCALE);
        float u1y = m1b ? 0.f : __expf(a.w * SCALE);
        *(__half2*)&Us[lr0 * PCH + lj]       = __floats2half2_rn(u0x, u0y);
        *(__half2*)&Us[(lr0 + 8) * PCH + lj] = __floats2half2_rn(u1x, u1y);
        sum0 += u0x + u0y;
        sum1 += u1x + u1y;
    }
    sum0 += __shfl_xor_sync(0xffffffffu, sum0, 1);
    sum0 += __shfl_xor_sync(0xffffffffu, sum0, 2);
    sum1 += __shfl_xor_sync(0xffffffffu, sum1, 1);
    sum1 += __shfl_xor_sync(0xffffffffu, sum1, 2);
    if ((lane & 3) == 0) {
        size_t base = (size_t)jt * NROWS + (size_t)(b * NH + n) * LL + r0g;
        g_tl[base] = sum0;
        g_tl[base + 8] = sum1;
    }
    __syncthreads();

    // ---- coalesced bulk store: 1024 uint4 (STG.128) ----
    const size_t srowbase = ((size_t)(b * NH + n) * LL + i0) * LL + j0;
#pragma unroll
    for (int t = 0; t < 4; t++) {
        int idx = tid + t * 256;
        int row = idx >> 3, c8 = idx & 7;
        *(uint4*)&g_scores[srowbase + (size_t)row * LL + c8 * 8] =
            *(const uint4*)&Us[row * PCH + c8 * 8];
    }
}

// ---------------------------------------------------------------------------
// Kernel 2: combine tile sums -> g_c = 1/L.
// ---------------------------------------------------------------------------
__global__ __launch_bounds__(256) void k_comb()
{
    const int r = blockIdx.x * 256 + threadIdx.x;
    float L = 0.f;
#pragma unroll
    for (int t = 0; t < NTJ; t++) L += g_tl[(size_t)t * NROWS + r];
    const int i = r & (LL - 1);
    const int n = (r >> 11) & (NH - 1);
    const int b = r >> 15;
    g_c[((size_t)(b * LL + i)) * NH + n] = 1.f / L;
}

// ---------------------------------------------------------------------------
// Kernel 3: attn output, v2. fp16 transpose buffer (fill = pure moves),
// c applied in f32 on the read side (bit-identical math). 512 thr x 3 CTAs/SM.
// 32i x 32j x 16n tile. Hs pitch 644 halves/jj row (LDS.64-aligned).
// ---------------------------------------------------------------------------
#define HP 644
#define SMEM_ATTN (32 * HP * 2 + 512 * 4)   // 41216 + 2048 = 43264 B
__global__ __launch_bounds__(512, 3) void k_attn(float* __restrict__ attn)
{
    extern __shared__ __half Hs[];                 // [32 jj][HP]: (jj, ii*20 + n)
    float* Cs = (float*)(Hs + 32 * HP);            // [32 ii][16 n]
    const int b = blockIdx.z, i0 = blockIdx.y * 32, j0 = blockIdx.x * 32;
    const int tid = threadIdx.x;

    Cs[tid] = g_c[(size_t)(b * LL + i0) * NH + tid];

    // ---- fill: raw fp16 u, transposed (pure data movement) ----
#pragma unroll
    for (int kk = 0; kk < 4; kk++) {
        int idx = tid + kk * 512;          // 2048 uint4
        int c8 = idx & 3, ii = (idx >> 2) & 31, n = idx >> 7;
        uint4 raw = *(const uint4*)&g_scores[
            (((size_t)(b * NH + n)) * LL + i0 + ii) * LL + j0 + c8 * 8];
        const __half* h = (const __half*)&raw;
        const int base = ii * 20 + n;
#pragma unroll
        for (int t = 0; t < 8; t++)
            Hs[(c8 * 8 + t) * HP + base] = h[t];
    }
    __syncthreads();

    // ---- read + scale + coalesced float4 store ----
#pragma unroll
    for (int kk = 0; kk < 8; kk++) {
        int idx = tid + kk * 512;          // 4096 float4
        int n4 = idx & 3, ii = (idx >> 2) & 31, jj = idx >> 7;
        const __half2* hp = (const __half2*)&Hs[jj * HP + ii * 20 + n4 * 4];
        float2 f0 = __half22float2(hp[0]);
        float2 f1 = __half22float2(hp[1]);
        float4 c = *(const float4*)&Cs[ii * 16 + n4 * 4];
        float4 o = make_float4(f0.x * c.x, f0.y * c.y, f1.x * c.z, f1.y * c.w);
        *(float4*)&attn[(((size_t)(b * LL + i0 + ii)) * LL + j0 + jj) * NH + n4 * 4] = o;
    }
}

// ---------------------------------------------------------------------------
// Kernel 4: tensor PV, cp.async double-buffered, fp16.
// CTA = (b,n) x 128 i. 8 warps, warp = 16 i x 64 d. ctx = c * (P_f16 @ Vh).
// ---------------------------------------------------------------------------
#define PVB_L 0
#define VVH_L (128 * PCH)
#define ST_ELEMS (128 * PCH + 64 * PCH)         // 13824 halves / stage
#define SMEM4_BYTES (2 * ST_ELEMS * 2)          // 55296 B

__global__ __launch_bounds__(256, 3) void k_pvt(float* __restrict__ ctx)
{
    extern __shared__ __half pb[];

    const int bn = blockIdx.x;           // b*16+n
    const int b = bn >> 4, n = bn & 15;
    const int i0 = blockIdx.y * 128;
    const int tid = threadIdx.x, w = tid >> 5, lane = tid & 31;

    float4 acc[8];
#pragma unroll
    for (int g = 0; g < 8; g++) acc[g] = make_float4(0.f, 0.f, 0.f, 0.f);

    const size_t ubase = ((size_t)bn * LL + i0) * LL;
    const size_t vbase = (size_t)bn * LL * DD;
    const uint32_t pb0 = smem_u32(pb);

    const int a_row = w * 16 + (lane & 15);
    const int a_kof = (lane >> 4) << 3;
    const int v_rof = ((lane >> 3) & 1) * 8 + (lane & 7);
    const int v_cof = (lane >> 4) * 8;

    auto issue = [&](int jt, int stage) {
        const uint32_t dst = pb0 + stage * (ST_ELEMS * 2);
        const int j0 = jt * 64;
        {
            int idx = tid;                 // 512 lines for V (2 per thread)
            int r = idx >> 3, c8 = idx & 7;
            cp_async16(dst + (VVH_L + r * PCH + c8 * 8) * 2,
                       &g_vh[vbase + (size_t)(j0 + r) * DD + c8 * 8]);
            idx = tid + 256;
            r = idx >> 3; c8 = idx & 7;
            cp_async16(dst + (VVH_L + r * PCH + c8 * 8) * 2,
                       &g_vh[vbase + (size_t)(j0 + r) * DD + c8 * 8]);
        }
#pragma unroll
        for (int t = 0; t < 4; t++) {
            int idx = tid + t * 256;       // 1024 lines for u
            int row = idx >> 3, c8 = idx & 7;
            cp_async16(dst + (PVB_L + row * PCH + c8 * 8) * 2,
                       &g_scores[ubase + (size_t)row * LL + j0 + c8 * 8]);
        }
        CP_COMMIT();
    };

    issue(0, 0);

    for (int jt = 0; jt < NTJ; jt++) {
        const int cur = jt & 1;
        if (jt + 1 < NTJ) {
            issue(jt + 1, cur ^ 1);
            CP_WAIT(1);
        } else {
            CP_WAIT(0);
        }
        __syncthreads();

        const __half* buf = pb + cur * ST_ELEMS;
#pragma unroll
        for (int ks = 0; ks < 4; ks++) {
            const int k0 = ks * 16;
            uint32_t ah[4];
            ldmatrix_x4(ah[0], ah[1], ah[2], ah[3],
                        smem_u32(&buf[PVB_L + a_row * PCH + k0 + a_kof]));
#pragma unroll
            for (int ng = 0; ng < 4; ng++) {
                uint32_t bh0, bh1, bh2, bh3;
                const int voff = (k0 + v_rof) * PCH + ng * 16 + v_cof;
                ldmatrix_x4_t(bh0, bh1, bh2, bh3, smem_u32(&buf[VVH_L + voff]));
                mma_f16(acc[ng * 2],     ah, bh0, bh1);
                mma_f16(acc[ng * 2 + 1], ah, bh2, bh3);
            }
        }
        __syncthreads();
    }

    const int r = w * 16 + (lane >> 2);
    const float c0 = g_c[((size_t)(b * LL + i0 + r)) * NH + n];
    const float c1 = g_c[((size_t)(b * LL + i0 + r + 8)) * NH + n];
#pragma unroll
    for (int ng = 0; ng < 8; ng++) {
        int colb = ng * 8 + (lane & 3) * 2;
        size_t g0 = (((size_t)(b * LL + i0 + r)) * NH + n) * DD + colb;
        size_t g1 = (((size_t)(b * LL + i0 + r + 8)) * NH + n) * DD + colb;
        *(float2*)&ctx[g0] = make_float2(acc[ng].x * c0, acc[ng].y * c0);
        *(float2*)&ctx[g1] = make_float2(acc[ng].z * c1, acc[ng].w * c1);
    }
}

// ---------------------------------------------------------------------------
extern "C" void kernel_launch(void* const* d_in, const int* in_sizes, int n_in,
                              void* d_out, int out_size)
{
    const float* q = (const float*)d_in[0];
    const float* k = (const float*)d_in[1];
    const float* v = (const float*)d_in[2];
    const int* mask = (const int*)d_in[3];

    float* ctx  = (float*)d_out;
    float* attn = (float*)d_out + (size_t)BB * LL * NH * DD;

    cudaFuncSetAttribute(k_scores, cudaFuncAttributeMaxDynamicSharedMemorySize, SMEM1_BYTES);
    cudaFuncSetAttribute(k_attn,   cudaFuncAttributeMaxDynamicSharedMemorySize, SMEM_ATTN);
    cudaFuncSetAttribute(k_pvt,    cudaFuncAttributeMaxDynamicSharedMemorySize, SMEM4_BYTES);

    k_prep<<<MASK_CTAS + (BB * NH * LL * 32) / 256, 256>>>(q, k, v, mask);

    dim3 g1(BB * NH, LL / TJ, LL / TI);
    k_scores<<<g1, 256, SMEM1_BYTES>>>();

    k_comb<<<NROWS / 256, 256>>>();

    dim3 ga(LL / 32, LL / 32, BB);
    k_attn<<<ga, 512, SMEM_ATTN>>>(attn);

    dim3 gp(BB * NH, LL / 128);
    k_pvt<<<gp, 256, SMEM4_BYTES>>>(ctx);
}

// round 17
// speedup vs baseline: 1.7512x; 1.0434x over previous
#include <cuda_runtime.h>
#include <cuda_fp16.h>
#include <math_constants.h>
#include <cstdint>

#define BB 2
#define LL 2048
#define NH 16
#define DD 64
#define SCALE 0.125f

#define TI 128
#define TJ 64
#define JCH 8                    // j-tiles per k_scores CTA
#define NJC 4                    // chunks per row (32 tiles / 8)
#define NROWS (BB * NH * LL)     // 65536 softmax rows
#define PCH 72                   // smem pitch in 16-bit elems (144B rows -> conflict-free LDSM)

// scores scratch: u = exp(masked scaled score) in fp16, layout [b][n][i][j]
__device__ __half g_scores[(size_t)BB * NH * LL * LL];
// per-(row, chunk) partial sums of u, layout [jc][b][n][i]
__device__ float g_tl[NJC * NROWS];
// final per-row 1/sum, layout [b][i][n]
__device__ float g_c[BB * LL * NH];
// fp16 operands, layout [b][n][j][d]
__device__ __half g_qh[(size_t)BB * NH * LL * DD];
__device__ __half g_kh[(size_t)BB * NH * LL * DD];
__device__ __half g_vh[(size_t)BB * NH * LL * DD];
// mask packed to bytes, layout [b][i][j]
__device__ unsigned char g_mask8[(size_t)BB * LL * LL];

// ---------------- portable tensor helpers (sm_80+) ----------------
__device__ __forceinline__ uint32_t smem_u32(const void* p) {
    uint32_t a;
    asm("{ .reg .u64 t; cvta.to.shared.u64 t, %1; cvt.u32.u64 %0, t; }" : "=r"(a) : "l"(p));
    return a;
}
__device__ __forceinline__ void ldmatrix_x4(uint32_t& r0, uint32_t& r1,
                                            uint32_t& r2, uint32_t& r3, uint32_t addr) {
    asm volatile("ldmatrix.sync.aligned.m8n8.x4.shared.b16 {%0,%1,%2,%3}, [%4];"
                 : "=r"(r0), "=r"(r1), "=r"(r2), "=r"(r3) : "r"(addr));
}
__device__ __forceinline__ void ldmatrix_x4_t(uint32_t& r0, uint32_t& r1,
                                              uint32_t& r2, uint32_t& r3, uint32_t addr) {
    asm volatile("ldmatrix.sync.aligned.m8n8.x4.trans.shared.b16 {%0,%1,%2,%3}, [%4];"
                 : "=r"(r0), "=r"(r1), "=r"(r2), "=r"(r3) : "r"(addr));
}
__device__ __forceinline__ void mma_f16(float4& d, const uint32_t a[4],
                                        uint32_t b0, uint32_t b1) {
    asm volatile(
        "mma.sync.aligned.m16n8k16.row.col.f32.f16.f16.f32 "
        "{%0,%1,%2,%3},{%4,%5,%6,%7},{%8,%9},{%0,%1,%2,%3};"
        : "+f"(d.x), "+f"(d.y), "+f"(d.z), "+f"(d.w)
        : "r"(a[0]), "r"(a[1]), "r"(a[2]), "r"(a[3]), "r"(b0), "r"(b1));
}
__device__ __forceinline__ void cp_async16(uint32_t smem, const void* gmem) {
    asm volatile("cp.async.cg.shared.global [%0], [%1], 16;" :: "r"(smem), "l"(gmem));
}
#define CP_COMMIT() asm volatile("cp.async.commit_group;" ::: "memory")
#define CP_WAIT(n)  asm volatile("cp.async.wait_group %0;" :: "n"(n) : "memory")

// ---------------------------------------------------------------------------
// Kernel 0: fused prep. CTAs [0,2048): pack mask int32 -> bytes.
//           CTAs [2048,10240): cast Q,K,V -> fp16, [b,i,n,d] -> [b,n,i,d].
// ---------------------------------------------------------------------------
#define MASK_CTAS 2048
__global__ __launch_bounds__(256) void k_prep(
    const float* __restrict__ q, const float* __restrict__ k,
    const float* __restrict__ v, const int* __restrict__ mask)
{
    if (blockIdx.x < MASK_CTAS) {
        size_t base = ((size_t)blockIdx.x * 256 + threadIdx.x) * 16;
        int4 a = *(const int4*)&mask[base];
        int4 b = *(const int4*)&mask[base + 4];
        int4 c = *(const int4*)&mask[base + 8];
        int4 d = *(const int4*)&mask[base + 12];
        uint4 o;
        o.x = (a.x ? 1u : 0u) | (a.y ? 0x100u : 0u) | (a.z ? 0x10000u : 0u) | (a.w ? 0x1000000u : 0u);
        o.y = (b.x ? 1u : 0u) | (b.y ? 0x100u : 0u) | (b.z ? 0x10000u : 0u) | (b.w ? 0x1000000u : 0u);
        o.z = (c.x ? 1u : 0u) | (c.y ? 0x100u : 0u) | (c.z ? 0x10000u : 0u) | (c.w ? 0x1000000u : 0u);
        o.w = (d.x ? 1u : 0u) | (d.y ? 0x100u : 0u) | (d.z ? 0x10000u : 0u) | (d.w ? 0x1000000u : 0u);
        *(uint4*)&g_mask8[base] = o;
    } else {
        int idx = (blockIdx.x - MASK_CTAS) * 256 + threadIdx.x;   // BB*NH*LL*32
        int d2 = idx & 31;
        int j  = (idx >> 5) & (LL - 1);
        int n  = (idx >> 16) & 15;
        int b  = idx >> 20;
        size_t src = (((size_t)(b * LL + j)) * NH + n) * DD + d2 * 2;
        size_t dst = (((size_t)(b * NH + n)) * LL + j) * DD + d2 * 2;
        float2 xq = *(const float2*)&q[src];
        float2 xk = *(const float2*)&k[src];
        float2 xv = *(const float2*)&v[src];
        *(__half2*)&g_qh[dst] = __floats2half2_rn(xq.x, xq.y);
        *(__half2*)&g_kh[dst] = __floats2half2_rn(xk.x, xk.y);
        *(__half2*)&g_vh[dst] = __floats2half2_rn(xv.x, xv.y);
    }
}

// k_scores smem layout (16-bit units unless noted)
#define QS_OFF 0                                  // [128][72]
#define KS_OFF (TI * PCH)                         // 2 x [64][72]
#define US_OFF (TI * PCH + 2 * TJ * PCH)          // [128][72]
#define MSKB_OFF ((2 * TI * PCH + 2 * TJ * PCH) * 2)  // bytes: 2 x [128*64]
#define SMEM1_BYTES (MSKB_OFF + 2 * TI * TJ)      // 55296 + 16384 = 71680 B

// ---------------------------------------------------------------------------
// Kernel 1: HMMA scores, j-chunk persistent. CTA = (b,n) x 128i x (8 j-tiles).
// Q resident in smem; K + mask double-buffered via cp.async. 8 warps, warp=16i.
// Row sums accumulate in regs across the chunk -> g_tl[jc].
// ---------------------------------------------------------------------------
__global__ __launch_bounds__(256, 3) void k_scores()
{
    extern __shared__ __half sb[];
    unsigned char* MskB = (unsigned char*)sb + MSKB_OFF;

    const int bn = blockIdx.x;
    const int b  = bn >> 4;
    const int jc = blockIdx.y;
    const int i0 = blockIdx.z * TI;
    const int jt0 = jc * JCH;
    const int tid  = threadIdx.x;
    const int w    = tid >> 5;
    const int lane = tid & 31;

    const size_t qbase = ((size_t)bn * LL + i0) * DD;
    const size_t kbase = (size_t)bn * LL * DD;
    const size_t mbase8 = (size_t)(b * LL + i0) * LL;
    const uint32_t sb0 = smem_u32(sb);

    // ---- stage loader for j-tile t (K tile + mask tile) ----
    auto issue = [&](int t, int s) {
        const int j0 = (jt0 + t) * TJ;
        const uint32_t kdst = sb0 + (KS_OFF + s * TJ * PCH) * 2;
        const uint32_t mdst = sb0 + MSKB_OFF + s * (TI * TJ);
#pragma unroll
        for (int rep = 0; rep < 2; rep++) {       // 512 lines K
            int idx = tid + rep * 256;
            int r = idx >> 3, c8 = idx & 7;
            cp_async16(kdst + (r * PCH + c8 * 8) * 2,
                       &g_kh[kbase + (size_t)(j0 + r) * DD + c8 * 8]);
        }
#pragma unroll
        for (int rep = 0; rep < 2; rep++) {       // 512 uint4 mask
            int idx = tid + rep * 256;
            int i = idx >> 2, c = idx & 3;
            cp_async16(mdst + i * 64 + c * 16,
                       &g_mask8[mbase8 + (size_t)i * LL + j0 + c * 16]);
        }
        CP_COMMIT();
    };

    issue(0, 0);

    // ---- load Q once (1024 uint4), resident for the whole chunk ----
#pragma unroll
    for (int t = 0; t < 4; t++) {
        int idx = tid + t * 256;
        int r = idx >> 3, c8 = idx & 7;
        *(uint4*)&sb[QS_OFF + r * PCH + c8 * 8] =
            *(const uint4*)&g_qh[qbase + (size_t)r * DD + c8 * 8];
    }

    const int a_row = w * 16 + (lane & 15);
    const int a_kof = (lane >> 4) << 3;
    const int b_row = ((lane >> 4) << 3) + (lane & 7);
    const int b_kof = ((lane >> 3) & 1) << 3;
    const int qr = lane >> 2, qc = (lane & 3) * 2;
    const int lr0 = w * 16 + qr;              // local row (second: +8)

    float sum0 = 0.f, sum1 = 0.f;

    for (int t = 0; t < JCH; t++) {
        const int cur = t & 1;
        if (t + 1 < JCH) {
            issue(t + 1, cur ^ 1);
            CP_WAIT(1);
        } else {
            CP_WAIT(0);
        }
        __syncthreads();

        const int ks_base = KS_OFF + cur * TJ * PCH;
        const unsigned char* Msk = MskB + cur * (TI * TJ);

        float4 acc[8];
#pragma unroll
        for (int jf = 0; jf < 8; jf++) acc[jf] = make_float4(0.f, 0.f, 0.f, 0.f);

#pragma unroll
        for (int ks = 0; ks < 4; ks++) {
            const int k0 = ks * 16;
            uint32_t ah[4];
            ldmatrix_x4(ah[0], ah[1], ah[2], ah[3],
                        smem_u32(&sb[QS_OFF + a_row * PCH + k0 + a_kof]));
#pragma unroll
            for (int jp = 0; jp < 4; jp++) {
                uint32_t bh0, bh1, bh2, bh3;
                ldmatrix_x4(bh0, bh1, bh2, bh3,
                            smem_u32(&sb[ks_base + (jp * 16 + b_row) * PCH + k0 + b_kof]));
                mma_f16(acc[jp * 2],     ah, bh0, bh1);
                mma_f16(acc[jp * 2 + 1], ah, bh2, bh3);
            }
        }

        // epilogue: u = exp(s) (masked -> 0), stage to Us, accumulate sums
        __half* Us = sb + US_OFF;
#pragma unroll
        for (int jf = 0; jf < 8; jf++) {
            const int lj = jf * 8 + qc;
            float4 a = acc[jf];
            unsigned char m0a = Msk[lr0 * 64 + lj],       m0b = Msk[lr0 * 64 + lj + 1];
            unsigned char m1a = Msk[(lr0 + 8) * 64 + lj], m1b = Msk[(lr0 + 8) * 64 + lj + 1];
            float u0x = m0a ? 0.f : __expf(a.x * SCALE);
            float u0y = m0b ? 0.f : __expf(a.y * SCALE);
            float u1x = m1a ? 0.f : __expf(a.z * SCALE);
            float u1y = m1b ? 0.f : __expf(a.w * SCALE);
            *(__half2*)&Us[lr0 * PCH + lj]       = __floats2half2_rn(u0x, u0y);
            *(__half2*)&Us[(lr0 + 8) * PCH + lj] = __floats2half2_rn(u1x, u1y);
            sum0 += u0x + u0y;
            sum1 += u1x + u1y;
        }
        __syncthreads();

        // coalesced bulk store: 1024 uint4 (STG.128)
        const size_t srowbase = ((size_t)bn * LL + i0) * LL + (jt0 + t) * TJ;
#pragma unroll
        for (int r4 = 0; r4 < 4; r4++) {
            int idx = tid + r4 * 256;
            int row = idx >> 3, c8 = idx & 7;
            *(uint4*)&g_scores[srowbase + (size_t)row * LL + c8 * 8] =
                *(const uint4*)&Us[row * PCH + c8 * 8];
        }
    }

    // chunk row sums -> g_tl[jc]
    sum0 += __shfl_xor_sync(0xffffffffu, sum0, 1);
    sum0 += __shfl_xor_sync(0xffffffffu, sum0, 2);
    sum1 += __shfl_xor_sync(0xffffffffu, sum1, 1);
    sum1 += __shfl_xor_sync(0xffffffffu, sum1, 2);
    if ((lane & 3) == 0) {
        size_t base = (size_t)jc * NROWS + (size_t)bn * LL + i0 + lr0;
        g_tl[base] = sum0;
        g_tl[base + 8] = sum1;
    }
}

// ---------------------------------------------------------------------------
// Kernel 2: combine chunk sums -> g_c = 1/L.
// ---------------------------------------------------------------------------
__global__ __launch_bounds__(256) void k_comb()
{
    const int r = blockIdx.x * 256 + threadIdx.x;
    float L = 0.f;
#pragma unroll
    for (int t = 0; t < NJC; t++) L += g_tl[(size_t)t * NROWS + r];
    const int i = r & (LL - 1);
    const int n = (r >> 11) & (NH - 1);
    const int b = r >> 15;
    g_c[((size_t)(b * LL + i)) * NH + n] = 1.f / L;
}

// ---------------------------------------------------------------------------
// Kernel 3: attn output. fp16 transpose buffer, c applied f32 on read side.
// 512 thr x 3 CTAs/SM. 32i x 32j x 16n tile. (At DRAM floor — frozen.)
// ---------------------------------------------------------------------------
#define HP 644
#define SMEM_ATTN (32 * HP * 2 + 512 * 4)   // 43264 B
__global__ __launch_bounds__(512, 3) void k_attn(float* __restrict__ attn)
{
    extern __shared__ __half Hs[];                 // [32 jj][HP]: (jj, ii*20 + n)
    float* Cs = (float*)(Hs + 32 * HP);            // [32 ii][16 n]
    const int b = blockIdx.z, i0 = blockIdx.y * 32, j0 = blockIdx.x * 32;
    const int tid = threadIdx.x;

    Cs[tid] = g_c[(size_t)(b * LL + i0) * NH + tid];

#pragma unroll
    for (int kk = 0; kk < 4; kk++) {
        int idx = tid + kk * 512;          // 2048 uint4
        int c8 = idx & 3, ii = (idx >> 2) & 31, n = idx >> 7;
        uint4 raw = *(const uint4*)&g_scores[
            (((size_t)(b * NH + n)) * LL + i0 + ii) * LL + j0 + c8 * 8];
        const __half* h = (const __half*)&raw;
        const int base = ii * 20 + n;
#pragma unroll
        for (int t = 0; t < 8; t++)
            Hs[(c8 * 8 + t) * HP + base] = h[t];
    }
    __syncthreads();

#pragma unroll
    for (int kk = 0; kk < 8; kk++) {
        int idx = tid + kk * 512;          // 4096 float4
        int n4 = idx & 3, ii = (idx >> 2) & 31, jj = idx >> 7;
        const __half2* hp = (const __half2*)&Hs[jj * HP + ii * 20 + n4 * 4];
        float2 f0 = __half22float2(hp[0]);
        float2 f1 = __half22float2(hp[1]);
        float4 c = *(const float4*)&Cs[ii * 16 + n4 * 4];
        float4 o = make_float4(f0.x * c.x, f0.y * c.y, f1.x * c.z, f1.y * c.w);
        *(float4*)&attn[(((size_t)(b * LL + i0 + ii)) * LL + j0 + jj) * NH + n4 * 4] = o;
    }
}

// ---------------------------------------------------------------------------
// Kernel 4: tensor PV, cp.async double-buffered, fp16.
// CTA = (b,n) x 128 i. 8 warps, warp = 16 i x 64 d. ctx = c * (P_f16 @ Vh).
// ---------------------------------------------------------------------------
#define NTJ_PV 32
#define PVB_L 0
#define VVH_L (128 * PCH)
#define ST_ELEMS (128 * PCH + 64 * PCH)         // 13824 halves / stage
#define SMEM4_BYTES (2 * ST_ELEMS * 2)          // 55296 B

__global__ __launch_bounds__(256, 3) void k_pvt(float* __restrict__ ctx)
{
    extern __shared__ __half pb[];

    const int bn = blockIdx.x;           // b*16+n
    const int b = bn >> 4, n = bn & 15;
    const int i0 = blockIdx.y * 128;
    const int tid = threadIdx.x, w = tid >> 5, lane = tid & 31;

    float4 acc[8];
#pragma unroll
    for (int g = 0; g < 8; g++) acc[g] = make_float4(0.f, 0.f, 0.f, 0.f);

    const size_t ubase = ((size_t)bn * LL + i0) * LL;
    const size_t vbase = (size_t)bn * LL * DD;
    const uint32_t pb0 = smem_u32(pb);

    const int a_row = w * 16 + (lane & 15);
    const int a_kof = (lane >> 4) << 3;
    const int v_rof = ((lane >> 3) & 1) * 8 + (lane & 7);
    const int v_cof = (lane >> 4) * 8;

    auto issue = [&](int jt, int stage) {
        const uint32_t dst = pb0 + stage * (ST_ELEMS * 2);
        const int j0 = jt * 64;
        {
            int idx = tid;
            int r = idx >> 3, c8 = idx & 7;
            cp_async16(dst + (VVH_L + r * PCH + c8 * 8) * 2,
                       &g_vh[vbase + (size_t)(j0 + r) * DD + c8 * 8]);
            idx = tid + 256;
            r = idx >> 3; c8 = idx & 7;
            cp_async16(dst + (VVH_L + r * PCH + c8 * 8) * 2,
                       &g_vh[vbase + (size_t)(j0 + r) * DD + c8 * 8]);
        }
#pragma unroll
        for (int t = 0; t < 4; t++) {
            int idx = tid + t * 256;
            int row = idx >> 3, c8 = idx & 7;
            cp_async16(dst + (PVB_L + row * PCH + c8 * 8) * 2,
                       &g_scores[ubase + (size_t)row * LL + j0 + c8 * 8]);
        }
        CP_COMMIT();
    };

    issue(0, 0);

    for (int jt = 0; jt < NTJ_PV; jt++) {
        const int cur = jt & 1;
        if (jt + 1 < NTJ_PV) {
            issue(jt + 1, cur ^ 1);
            CP_WAIT(1);
        } else {
            CP_WAIT(0);
        }
        __syncthreads();

        const __half* buf = pb + cur * ST_ELEMS;
#pragma unroll
        for (int ks = 0; ks < 4; ks++) {
            const int k0 = ks * 16;
            uint32_t ah[4];
            ldmatrix_x4(ah[0], ah[1], ah[2], ah[3],
                        smem_u32(&buf[PVB_L + a_row * PCH + k0 + a_kof]));
#pragma unroll
            for (int ng = 0; ng < 4; ng++) {
                uint32_t bh0, bh1, bh2, bh3;
                const int voff = (k0 + v_rof) * PCH + ng * 16 + v_cof;
                ldmatrix_x4_t(bh0, bh1, bh2, bh3, smem_u32(&buf[VVH_L + voff]));
                mma_f16(acc[ng * 2],     ah, bh0, bh1);
                mma_f16(acc[ng * 2 + 1], ah, bh2, bh3);
            }
        }
        __syncthreads();
    }

    const int r = w * 16 + (lane >> 2);
    const float c0 = g_c[((size_t)(b * LL + i0 + r)) * NH + n];
    const float c1 = g_c[((size_t)(b * LL + i0 + r + 8)) * NH + n];
#pragma unroll
    for (int ng = 0; ng < 8; ng++) {
        int colb = ng * 8 + (lane & 3) * 2;
        size_t g0 = (((size_t)(b * LL + i0 + r)) * NH + n) * DD + colb;
        size_t g1 = (((size_t)(b * LL + i0 + r + 8)) * NH + n) * DD + colb;
        *(float2*)&ctx[g0] = make_float2(acc[ng].x * c0, acc[ng].y * c0);
        *(float2*)&ctx[g1] = make_float2(acc[ng].z * c1, acc[ng].w * c1);
    }
}

// ---------------------------------------------------------------------------
extern "C" void kernel_launch(void* const* d_in, const int* in_sizes, int n_in,
                              void* d_out, int out_size)
{
    const float* q = (const float*)d_in[0];
    const float* k = (const float*)d_in[1];
    const float* v = (const float*)d_in[2];
    const int* mask = (const int*)d_in[3];

    float* ctx  = (float*)d_out;
    float* attn = (float*)d_out + (size_t)BB * LL * NH * DD;

    cudaFuncSetAttribute(k_scores, cudaFuncAttributeMaxDynamicSharedMemorySize, SMEM1_BYTES);
    cudaFuncSetAttribute(k_attn,   cudaFuncAttributeMaxDynamicSharedMemorySize, SMEM_ATTN);
    cudaFuncSetAttribute(k_pvt,    cudaFuncAttributeMaxDynamicSharedMemorySize, SMEM4_BYTES);

    k_prep<<<MASK_CTAS + (BB * NH * LL * 32) / 256, 256>>>(q, k, v, mask);

    dim3 g1(BB * NH, NJC, LL / TI);
    k_scores<<<g1, 256, SMEM1_BYTES>>>();

    k_comb<<<NROWS / 256, 256>>>();

    dim3 ga(LL / 32, LL / 32, BB);
    k_attn<<<ga, 512, SMEM_ATTN>>>(attn);

    dim3 gp(BB * NH, LL / 128);
    k_pvt<<<gp, 256, SMEM4_BYTES>>>(ctx);
}